// round 9
// baseline (speedup 1.0000x reference)
#include <cuda_runtime.h>
#include <cuda_fp16.h>
#include <math.h>
#include <stdint.h>

// Problem constants
constexpr int Bn  = 4;
constexpr int Sn  = 2048;
constexpr int Dn  = 1024;
constexpr int HDn = 64;
constexpr int FFn = 4096;
constexpr int Mn  = Bn * Sn;        // 8192 rows
constexpr float NEG_INF = -1.0e30f;

// ---------------- scratch (static __device__, no allocations) ----------------
__device__ __half g_WqkvT[3 * Dn * Dn];        // [N=3072][K=1024] K-major, fp16
__device__ float  g_Bqkv [3 * Dn];
__device__ __half g_WoT  [Dn * Dn];
__device__ __half g_W1T  [FFn * Dn];
__device__ __half g_W2T  [Dn * FFn];
__device__ __half g_xh  [(size_t)Mn * Dn];     // fp16 copy of x
__device__ __half g_QKVh[(size_t)Mn * 3 * Dn]; // q|k|v per row (fp16)
__device__ __half g_Vth [(size_t)64 * HDn * Sn]; // V transposed: [bh][hd][s]
__device__ __half g_Oh  [(size_t)Mn * Dn];     // attention out (fp16)
__device__ float  g_T   [(size_t)Mn * Dn];     // residual temp
__device__ float  g_Hh  [(size_t)Mn * Dn];     // post-LN1 hidden (fp32)
__device__ __half g_Hhh [(size_t)Mn * Dn];     // post-LN1 hidden (fp16)
__device__ __half g_FFh [(size_t)Mn * FFn];    // FFN intermediate (fp16)

// ---------------- helpers ----------------
__device__ __forceinline__ uint32_t smem_u32(const void* p) {
    return (uint32_t)__cvta_generic_to_shared(p);
}
__device__ __forceinline__ void cpasync16(uint32_t dst, const void* src) {
    asm volatile("cp.async.ca.shared.global [%0], [%1], 16;" :: "r"(dst), "l"(src) : "memory");
}
__device__ __forceinline__ void cp_commit() {
    asm volatile("cp.async.commit_group;" ::: "memory");
}
__device__ __forceinline__ void mma_f16(float* c, const uint32_t* a, const uint32_t* b) {
    asm volatile(
        "mma.sync.aligned.m16n8k16.row.col.f32.f16.f16.f32 "
        "{%0,%1,%2,%3}, {%4,%5,%6,%7}, {%8,%9}, {%0,%1,%2,%3};"
        : "+f"(c[0]), "+f"(c[1]), "+f"(c[2]), "+f"(c[3])
        : "r"(a[0]), "r"(a[1]), "r"(a[2]), "r"(a[3]), "r"(b[0]), "r"(b[1]));
}
__device__ __forceinline__ void ldsm_x4(uint32_t* r, uint32_t addr) {
    asm volatile("ldmatrix.sync.aligned.m8n8.x4.shared.b16 {%0,%1,%2,%3}, [%4];"
                 : "=r"(r[0]), "=r"(r[1]), "=r"(r[2]), "=r"(r[3]) : "r"(addr));
}

// ---------------- weight/activation repacks ----------------
__global__ void repack_qkvT(const float* __restrict__ wq, const float* __restrict__ wk,
                            const float* __restrict__ wv, const float* __restrict__ bq,
                            const float* __restrict__ bk, const float* __restrict__ bv) {
    int gid = blockIdx.x * blockDim.x + threadIdx.x;
    if (gid < 3 * Dn * Dn) {
        int n = gid >> 10;
        int d = gid & 1023;
        int which = n >> 10;
        int c = n & 1023;
        int h = c >> 6, f = c & 63;
        const float* w = (which == 0) ? wq : (which == 1) ? wk : wv;
        g_WqkvT[gid] = __float2half(w[((size_t)h * Dn + d) * HDn + f]);
    }
    if (gid < 3 * Dn) {
        int which = gid >> 10; int c = gid & 1023;
        const float* b = (which == 0) ? bq : (which == 1) ? bk : bv;
        g_Bqkv[gid] = b[c];
    }
}

__global__ void transpose_kh(__half* __restrict__ dst, const float* __restrict__ src,
                             int R, int C) {
    __shared__ float tile[32][33];
    int c0 = blockIdx.x * 32, r0 = blockIdx.y * 32;
    int tx = threadIdx.x, ty = threadIdx.y;
    #pragma unroll
    for (int i = 0; i < 32; i += 8)
        tile[ty + i][tx] = src[(size_t)(r0 + ty + i) * C + c0 + tx];
    __syncthreads();
    #pragma unroll
    for (int i = 0; i < 32; i += 8)
        dst[(size_t)(c0 + ty + i) * R + r0 + tx] = __float2half(tile[tx][ty + i]);
}

__global__ void f2h(const float* __restrict__ X, __half* __restrict__ Y, int n4) {
    int i = blockIdx.x * blockDim.x + threadIdx.x;
    if (i < n4) {
        float4 v = *(const float4*)(X + (size_t)i * 4);
        __half2 h0 = __floats2half2_rn(v.x, v.y);
        __half2 h1 = __floats2half2_rn(v.z, v.w);
        *(uint2*)(Y + (size_t)i * 4) = make_uint2(*(uint32_t*)&h0, *(uint32_t*)&h1);
    }
}

// V per-head transpose: Vth[(bh*64 + f)*S + s] = QKVh[(b*S+s)*3072 + 2048 + h*64 + f]
__global__ void vtrans(const __half* __restrict__ QKVh, __half* __restrict__ Vth) {
    __shared__ __half tile[32][33];
    int bh = blockIdx.z, b = bh >> 4, h = bh & 15;
    int s0 = blockIdx.x * 32, f0 = blockIdx.y * 32;
    int tx = threadIdx.x, ty = threadIdx.y;
    #pragma unroll
    for (int i = 0; i < 32; i += 8)
        tile[ty + i][tx] = QKVh[(size_t)(b * Sn + s0 + ty + i) * 3072 + 2048 + h * 64 + f0 + tx];
    __syncthreads();
    #pragma unroll
    for (int i = 0; i < 32; i += 8)
        Vth[((size_t)bh * 64 + f0 + ty + i) * Sn + s0 + tx] = tile[tx][ty + i];
}

// ---------------- fp16 tensor GEMM 128x128x64, cp.async double buffer --------
// 128 threads = 4 warps (2m x 2n); warp tile 64x64 = 4x8 m16n8k16 tiles.
// SMEM rows of 72 halves -> conflict-free STS and LDSM.
enum { EPI_BIAS = 0, EPI_GELUH = 1, EPI_RES = 2, EPI_BIASH = 3 };

__device__ __forceinline__ float gelu_f(float x) {
    return 0.5f * x * (1.0f + erff(x * 0.70710678118654752440f));
}

constexpr int GSTR = 72;                          // smem row stride (halves)
constexpr int G_BUF_H = 128 * GSTR;               // 9216 halves per matrix buf
constexpr int GEMM_SMEM = 4 * G_BUF_H * 2;        // A0,A1,B0,B1 = 73728 B

template <int EPI>
__global__ void __launch_bounds__(128, 2)
hgemm(const __half* __restrict__ A, const __half* __restrict__ Bt,
      const float* __restrict__ bias, const float* __restrict__ Res,
      float* __restrict__ C, __half* __restrict__ Ch, int M, int N, int K) {
    extern __shared__ __half sh[];
    const uint32_t sB = smem_u32(sh);
    // layout (halves): A0 @0, A1 @9216, B0 @18432, B1 @27648

    const int tid  = threadIdx.x;
    const int lane = tid & 31, wid = tid >> 5;
    const int quad = lane >> 2, qt = lane & 3;
    const int wm = wid & 1, wn = wid >> 1;
    const int m0 = blockIdx.y * 128, n0 = blockIdx.x * 128;

    // LDSM per-thread offsets (bytes) within a buffer
    uint32_t aOff[4], bOff[4];
    {
        const int ar = (lane & 7) + ((lane >> 3) & 1) * 8;
        const int ak = (lane >> 4) * 8;
        #pragma unroll
        for (int mt = 0; mt < 4; mt++)
            aOff[mt] = ((wm * 64 + mt * 16 + ar) * GSTR + ak) * 2;
        const int br = (lane & 7) + ((lane >> 4) & 1) * 8;
        const int bk = ((lane >> 3) & 1) * 8;
        #pragma unroll
        for (int np = 0; np < 4; np++)
            bOff[np] = ((wn * 64 + np * 16 + br) * GSTR + bk) * 2;
    }

    float acc[4][8][4] = {};

    auto load_tile = [&](int kt, int buf) {
        const uint32_t aB = sB + (buf ? G_BUF_H : 0) * 2;
        const uint32_t bB = sB + ((buf ? 3 : 2) * G_BUF_H) * 2;
        const __half* Ap = A  + (size_t)m0 * K + (size_t)kt * 64;
        const __half* Bp = Bt + (size_t)n0 * K + (size_t)kt * 64;
        #pragma unroll
        for (int i = 0; i < 8; i++) {
            int id = tid + i * 128;           // 0..1023
            int row = id >> 3, c = (id & 7) * 8;
            cpasync16(aB + (row * GSTR + c) * 2, Ap + (size_t)row * K + c);
        }
        #pragma unroll
        for (int i = 0; i < 8; i++) {
            int id = tid + i * 128;
            int row = id >> 3, c = (id & 7) * 8;
            cpasync16(bB + (row * GSTR + c) * 2, Bp + (size_t)row * K + c);
        }
        cp_commit();
    };

    const int NT = K >> 6;
    load_tile(0, 0);

    for (int kt = 0; kt < NT; kt++) {
        const int buf = kt & 1;
        if (kt + 1 < NT) {
            load_tile(kt + 1, buf ^ 1);
            asm volatile("cp.async.wait_group 1;" ::: "memory");
        } else {
            asm volatile("cp.async.wait_group 0;" ::: "memory");
        }
        __syncthreads();

        const uint32_t AbU = sB + (buf ? G_BUF_H : 0) * 2;
        const uint32_t BbU = sB + ((buf ? 3 : 2) * G_BUF_H) * 2;
        #pragma unroll
        for (int ks = 0; ks < 4; ks++) {
            const uint32_t kbB = ks * 16 * 2;
            uint32_t af[4][4], bf4[4][4];
            #pragma unroll
            for (int mt = 0; mt < 4; mt++)
                ldsm_x4(af[mt], AbU + aOff[mt] + kbB);
            #pragma unroll
            for (int np = 0; np < 4; np++)
                ldsm_x4(bf4[np], BbU + bOff[np] + kbB);
            #pragma unroll
            for (int mt = 0; mt < 4; mt++)
                #pragma unroll
                for (int nt = 0; nt < 8; nt++)
                    mma_f16(acc[mt][nt], af[mt], &bf4[nt >> 1][(nt & 1) * 2]);
        }
        __syncthreads();
    }

    #pragma unroll
    for (int mt = 0; mt < 4; mt++) {
        const int r0 = m0 + wm * 64 + mt * 16 + quad;
        #pragma unroll
        for (int nt = 0; nt < 8; nt++) {
            const int col = n0 + wn * 64 + nt * 8 + qt * 2;
            const float2 bv2 = *(const float2*)&bias[col];
            #pragma unroll
            for (int half = 0; half < 2; half++) {
                const int r = r0 + half * 8;
                float2 y;
                y.x = acc[mt][nt][half * 2 + 0] + bv2.x;
                y.y = acc[mt][nt][half * 2 + 1] + bv2.y;
                size_t base = (size_t)r * N + col;
                if (EPI == EPI_GELUH) {
                    y.x = gelu_f(y.x); y.y = gelu_f(y.y);
                    __half2 hh = __floats2half2_rn(y.x, y.y);
                    *(__half2*)&Ch[base] = hh;
                } else if (EPI == EPI_BIASH) {
                    __half2 hh = __floats2half2_rn(y.x, y.y);
                    *(__half2*)&Ch[base] = hh;
                } else if (EPI == EPI_RES) {
                    float2 rr = *(const float2*)&Res[base];
                    y.x += rr.x; y.y += rr.y;
                    *(float2*)&C[base] = y;
                } else {
                    *(float2*)&C[base] = y;
                }
            }
        }
    }
}

// ---------------- tensor-core causal flash attention v2 ----------------------
// 256 threads = 8 warps; CTA = 128 query rows x one (b,h); warp = 16 rows.
// K/V tiles of 64 keys double-buffered; LDSM fragments; causal warp-skip.
constexpr int FSTR = 72;
constexpr int FA_Q_H  = 128 * FSTR;               // 9216
constexpr int FA_KV_H = 64 * FSTR;                // 4608
constexpr int FA_SMEM = (FA_Q_H + 4 * FA_KV_H) * 2;   // 55296 B

__global__ void __launch_bounds__(256, 2)
fattn(const __half* __restrict__ QKVh, const __half* __restrict__ Vth,
      __half* __restrict__ O) {
    extern __shared__ __half fs[];
    const uint32_t sB = smem_u32(fs);
    // halves layout: Q @0, K0 @9216, K1 @13824, V0 @18432, V1 @23040

    const int tid = threadIdx.x;
    const int lane = tid & 31, wid = tid >> 5;
    const int q4 = lane >> 2, qt2 = (lane & 3) * 2;
    const int qtile = gridDim.x - 1 - blockIdx.x;    // big tiles first
    const int bh = blockIdx.y, b = bh >> 4, h = bh & 15;
    const int r0 = qtile * 128;

    const int ar = (lane & 7) + ((lane >> 3) & 1) * 8;
    const int ak = (lane >> 4) * 8;
    const int br = (lane & 7) + ((lane >> 4) & 1) * 8;
    const int bk = ((lane >> 3) & 1) * 8;

    // load Q (128 rows x 64 halves)
    {
        const __half* Qg = QKVh + ((size_t)(b * Sn + r0)) * 3072 + h * 64;
        #pragma unroll
        for (int i = 0; i < 4; i++) {
            int id = tid + i * 256;          // 0..1023
            int row = id >> 3, c = (id & 7) * 8;
            cpasync16(sB + (row * FSTR + c) * 2, Qg + (size_t)row * 3072 + c);
        }
        cp_commit();
    }

    auto loadKV = [&](int kt, int buf) {
        const __half* Kg = QKVh + ((size_t)(b * Sn + kt * 64)) * 3072 + 1024 + h * 64;
        const __half* Vg = Vth + ((size_t)bh * 64) * Sn + kt * 64;
        const uint32_t kB = sB + (FA_Q_H + buf * FA_KV_H) * 2;
        const uint32_t vB = sB + (FA_Q_H + (2 + buf) * FA_KV_H) * 2;
        #pragma unroll
        for (int i = 0; i < 2; i++) {
            int id = tid + i * 256;          // 0..511
            int row = id >> 3, c = (id & 7) * 8;
            cpasync16(kB + (row * FSTR + c) * 2, Kg + (size_t)row * 3072 + c);
            cpasync16(vB + (row * FSTR + c) * 2, Vg + (size_t)row * Sn + c);
        }
        cp_commit();
    };

    loadKV(0, 0);

    asm volatile("cp.async.wait_group 1;" ::: "memory");   // Q ready
    __syncthreads();
    uint32_t aQ[4][4];
    #pragma unroll
    for (int kcc = 0; kcc < 4; kcc++)
        ldsm_x4(aQ[kcc], sB + ((wid * 16 + ar) * FSTR + kcc * 16 + ak) * 2);

    const int rowg0 = r0 + wid * 16 + q4;
    const int rowg1 = rowg0 + 8;
    const int wrow_max = r0 + wid * 16 + 15;

    float m0 = NEG_INF, m1 = NEG_INF, l0 = 0.f, l1 = 0.f;
    float o[8][4] = {};

    const int ntk = 2 * qtile + 2;
    for (int kt = 0; kt < ntk; kt++) {
        const int buf = kt & 1;
        if (kt + 1 < ntk) {
            loadKV(kt + 1, buf ^ 1);
            asm volatile("cp.async.wait_group 1;" ::: "memory");
        } else {
            asm volatile("cp.async.wait_group 0;" ::: "memory");
        }
        __syncthreads();

        const int gk0 = kt * 64;
        if (gk0 <= wrow_max) {
            const uint32_t kB = sB + (FA_Q_H + buf * FA_KV_H) * 2;
            const uint32_t vB = sB + (FA_Q_H + (2 + buf) * FA_KV_H) * 2;

            float s[8][4] = {};
            #pragma unroll
            for (int kcc = 0; kcc < 4; kcc++) {
                uint32_t bf4[4][4];
                #pragma unroll
                for (int np = 0; np < 4; np++)
                    ldsm_x4(bf4[np], kB + ((np * 16 + br) * FSTR + kcc * 16 + bk) * 2);
                #pragma unroll
                for (int nt = 0; nt < 8; nt++)
                    mma_f16(s[nt], aQ[kcc], &bf4[nt >> 1][(nt & 1) * 2]);
            }

            const int colb = gk0 + qt2;
            float mx0 = NEG_INF, mx1 = NEG_INF;
            #pragma unroll
            for (int nt = 0; nt < 8; nt++) {
                const int c0 = colb + nt * 8;
                s[nt][0] = (c0     <= rowg0) ? s[nt][0] * 0.125f : NEG_INF;
                s[nt][1] = (c0 + 1 <= rowg0) ? s[nt][1] * 0.125f : NEG_INF;
                s[nt][2] = (c0     <= rowg1) ? s[nt][2] * 0.125f : NEG_INF;
                s[nt][3] = (c0 + 1 <= rowg1) ? s[nt][3] * 0.125f : NEG_INF;
                mx0 = fmaxf(mx0, fmaxf(s[nt][0], s[nt][1]));
                mx1 = fmaxf(mx1, fmaxf(s[nt][2], s[nt][3]));
            }
            mx0 = fmaxf(mx0, __shfl_xor_sync(0xffffffffu, mx0, 1));
            mx0 = fmaxf(mx0, __shfl_xor_sync(0xffffffffu, mx0, 2));
            mx1 = fmaxf(mx1, __shfl_xor_sync(0xffffffffu, mx1, 1));
            mx1 = fmaxf(mx1, __shfl_xor_sync(0xffffffffu, mx1, 2));

            const float mn0 = fmaxf(m0, mx0), mn1 = fmaxf(m1, mx1);
            const float sc0 = __expf(m0 - mn0), sc1 = __expf(m1 - mn1);
            m0 = mn0; m1 = mn1;

            float rs0 = 0.f, rs1 = 0.f;
            uint32_t pf[4][4];
            #pragma unroll
            for (int nt = 0; nt < 8; nt++) {
                float p0 = __expf(s[nt][0] - m0);
                float p1 = __expf(s[nt][1] - m0);
                float p2 = __expf(s[nt][2] - m1);
                float p3 = __expf(s[nt][3] - m1);
                rs0 += p0 + p1; rs1 += p2 + p3;
                __half2 h01 = __floats2half2_rn(p0, p1);
                __half2 h23 = __floats2half2_rn(p2, p3);
                pf[nt >> 1][(nt & 1) * 2 + 0] = *(uint32_t*)&h01;
                pf[nt >> 1][(nt & 1) * 2 + 1] = *(uint32_t*)&h23;
            }
            rs0 += __shfl_xor_sync(0xffffffffu, rs0, 1);
            rs0 += __shfl_xor_sync(0xffffffffu, rs0, 2);
            rs1 += __shfl_xor_sync(0xffffffffu, rs1, 1);
            rs1 += __shfl_xor_sync(0xffffffffu, rs1, 2);
            l0 = l0 * sc0 + rs0;
            l1 = l1 * sc1 + rs1;

            #pragma unroll
            for (int nt = 0; nt < 8; nt++) {
                o[nt][0] *= sc0; o[nt][1] *= sc0;
                o[nt][2] *= sc1; o[nt][3] *= sc1;
            }

            #pragma unroll
            for (int kcc = 0; kcc < 4; kcc++) {
                uint32_t bf4[4][4];
                #pragma unroll
                for (int np = 0; np < 4; np++)
                    ldsm_x4(bf4[np], vB + ((np * 16 + br) * FSTR + kcc * 16 + bk) * 2);
                #pragma unroll
                for (int nt = 0; nt < 8; nt++)
                    mma_f16(o[nt], pf[kcc], &bf4[nt >> 1][(nt & 1) * 2]);
            }
        }
        __syncthreads();
    }

    const float li0 = 1.0f / l0, li1 = 1.0f / l1;
    __half* Op0 = O + ((size_t)(b * Sn + rowg0)) * Dn + h * 64 + qt2;
    __half* Op1 = O + ((size_t)(b * Sn + rowg1)) * Dn + h * 64 + qt2;
    #pragma unroll
    for (int nt = 0; nt < 8; nt++) {
        __half2 h0 = __floats2half2_rn(o[nt][0] * li0, o[nt][1] * li0);
        __half2 h1 = __floats2half2_rn(o[nt][2] * li1, o[nt][3] * li1);
        *(__half2*)(Op0 + nt * 8) = h0;
        *(__half2*)(Op1 + nt * 8) = h1;
    }
}

// ---------------- LayerNorm: one block per row of 1024 -----------------------
__global__ void __launch_bounds__(256)
ln_kernel(const float* __restrict__ X, const float* __restrict__ G,
          const float* __restrict__ Bt, float* __restrict__ Y,
          __half* __restrict__ Yh) {
    const int row = blockIdx.x;
    const int t = threadIdx.x;
    const float* x = X + (size_t)row * Dn;

    float4 v = *(const float4*)(x + t * 4);
    float s  = v.x + v.y + v.z + v.w;
    float sq = v.x * v.x + v.y * v.y + v.z * v.z + v.w * v.w;
    #pragma unroll
    for (int off = 16; off; off >>= 1) {
        s  += __shfl_xor_sync(0xffffffffu, s,  off);
        sq += __shfl_xor_sync(0xffffffffu, sq, off);
    }
    __shared__ float rs[8], rq[8];
    int wid = t >> 5, lane = t & 31;
    if (lane == 0) { rs[wid] = s; rq[wid] = sq; }
    __syncthreads();
    if (t == 0) {
        float S = 0.f, Q = 0.f;
        #pragma unroll
        for (int i = 0; i < 8; i++) { S += rs[i]; Q += rq[i]; }
        float mean = S * (1.0f / Dn);
        float var  = Q * (1.0f / Dn) - mean * mean;
        rs[0] = mean;
        rq[0] = rsqrtf(var + 1e-5f);
    }
    __syncthreads();
    const float mean = rs[0], rstd = rq[0];

    float4 gv = *(const float4*)(G + t * 4);
    float4 bv = *(const float4*)(Bt + t * 4);
    float4 y;
    y.x = (v.x - mean) * rstd * gv.x + bv.x;
    y.y = (v.y - mean) * rstd * gv.y + bv.y;
    y.z = (v.z - mean) * rstd * gv.z + bv.z;
    y.w = (v.w - mean) * rstd * gv.w + bv.w;
    *(float4*)(Y + (size_t)row * Dn + t * 4) = y;
    if (Yh) {
        __half2 h0 = __floats2half2_rn(y.x, y.y);
        __half2 h1 = __floats2half2_rn(y.z, y.w);
        *(uint2*)(Yh + (size_t)row * Dn + t * 4) =
            make_uint2(*(uint32_t*)&h0, *(uint32_t*)&h1);
    }
}

// ---------------- launch ----------------
extern "C" void kernel_launch(void* const* d_in, const int* in_sizes, int n_in,
                              void* d_out, int out_size) {
    const float* x   = (const float*)d_in[0];
    const float* wq  = (const float*)d_in[1];
    const float* bq  = (const float*)d_in[2];
    const float* wk  = (const float*)d_in[3];
    const float* bk  = (const float*)d_in[4];
    const float* wv  = (const float*)d_in[5];
    const float* bv  = (const float*)d_in[6];
    const float* wo  = (const float*)d_in[7];
    const float* bo  = (const float*)d_in[8];
    const float* w1  = (const float*)d_in[9];
    const float* b1  = (const float*)d_in[10];
    const float* w2  = (const float*)d_in[11];
    const float* b2  = (const float*)d_in[12];
    const float* g1  = (const float*)d_in[13];
    const float* be1 = (const float*)d_in[14];
    const float* g2  = (const float*)d_in[15];
    const float* be2 = (const float*)d_in[16];

    __half *WqkvT, *WoT, *W1T, *W2T, *xh, *QKVh, *Vth, *Oh, *Hhh, *FFh;
    float *Bqkv, *T, *Hh;
    cudaGetSymbolAddress((void**)&WqkvT, g_WqkvT);
    cudaGetSymbolAddress((void**)&Bqkv,  g_Bqkv);
    cudaGetSymbolAddress((void**)&WoT,   g_WoT);
    cudaGetSymbolAddress((void**)&W1T,   g_W1T);
    cudaGetSymbolAddress((void**)&W2T,   g_W2T);
    cudaGetSymbolAddress((void**)&xh,    g_xh);
    cudaGetSymbolAddress((void**)&QKVh,  g_QKVh);
    cudaGetSymbolAddress((void**)&Vth,   g_Vth);
    cudaGetSymbolAddress((void**)&Oh,    g_Oh);
    cudaGetSymbolAddress((void**)&T,     g_T);
    cudaGetSymbolAddress((void**)&Hh,    g_Hh);
    cudaGetSymbolAddress((void**)&Hhh,   g_Hhh);
    cudaGetSymbolAddress((void**)&FFh,   g_FFh);

    cudaFuncSetAttribute(hgemm<EPI_BIASH>, cudaFuncAttributeMaxDynamicSharedMemorySize, GEMM_SMEM);
    cudaFuncSetAttribute(hgemm<EPI_GELUH>, cudaFuncAttributeMaxDynamicSharedMemorySize, GEMM_SMEM);
    cudaFuncSetAttribute(hgemm<EPI_RES>,   cudaFuncAttributeMaxDynamicSharedMemorySize, GEMM_SMEM);
    cudaFuncSetAttribute(fattn, cudaFuncAttributeMaxDynamicSharedMemorySize, FA_SMEM);

    // 0) weight repacks + x -> fp16
    repack_qkvT<<<(3 * Dn * Dn + 255) / 256, 256>>>(wq, wk, wv, bq, bk, bv);
    transpose_kh<<<dim3(Dn / 32, Dn / 32),  dim3(32, 8)>>>(WoT, wo, Dn, Dn);
    transpose_kh<<<dim3(FFn / 32, Dn / 32), dim3(32, 8)>>>(W1T, w1, Dn, FFn);
    transpose_kh<<<dim3(Dn / 32, FFn / 32), dim3(32, 8)>>>(W2T, w2, FFn, Dn);
    f2h<<<(Mn * Dn / 4 + 255) / 256, 256>>>(x, xh, Mn * Dn / 4);

    // 1) QKV projection -> fp16
    hgemm<EPI_BIASH><<<dim3(3 * Dn / 128, Mn / 128), 128, GEMM_SMEM>>>(
        xh, WqkvT, Bqkv, nullptr, nullptr, QKVh, Mn, 3 * Dn, Dn);
    // 1b) V transpose per head
    vtrans<<<dim3(Sn / 32, HDn / 32, 64), dim3(32, 8)>>>(QKVh, Vth);
    // 2) tensor-core causal flash attention -> Oh (fp16)
    fattn<<<dim3(Sn / 128, 64), 256, FA_SMEM>>>(QKVh, Vth, Oh);
    // 3) O projection + residual x
    hgemm<EPI_RES><<<dim3(Dn / 128, Mn / 128), 128, GEMM_SMEM>>>(
        Oh, WoT, bo, x, T, nullptr, Mn, Dn, Dn);
    // 4) LayerNorm 1 (fp32 + fp16 twin)
    ln_kernel<<<Mn, 256>>>(T, g1, be1, Hh, Hhh);
    // 5) FFN up + exact GELU -> fp16
    hgemm<EPI_GELUH><<<dim3(FFn / 128, Mn / 128), 128, GEMM_SMEM>>>(
        Hhh, W1T, b1, nullptr, nullptr, FFh, Mn, FFn, Dn);
    // 6) FFN down + residual Hh
    hgemm<EPI_RES><<<dim3(Dn / 128, Mn / 128), 128, GEMM_SMEM>>>(
        FFh, W2T, b2, Hh, T, nullptr, Mn, Dn, FFn);
    // 7) LayerNorm 2 -> output
    ln_kernel<<<Mn, 256>>>(T, g2, be2, (float*)d_out, nullptr);
}

// round 10
// speedup vs baseline: 1.0249x; 1.0249x over previous
#include <cuda_runtime.h>
#include <cuda_fp16.h>
#include <math.h>
#include <stdint.h>

// Problem constants
constexpr int Bn  = 4;
constexpr int Sn  = 2048;
constexpr int Dn  = 1024;
constexpr int HDn = 64;
constexpr int FFn = 4096;
constexpr int Mn  = Bn * Sn;        // 8192 rows
constexpr float NEG_INF = -1.0e30f;

// ---------------- scratch (static __device__, no allocations) ----------------
__device__ __half g_WqkvT[3 * Dn * Dn];        // [N=3072][K=1024] K-major, fp16
__device__ float  g_Bqkv [3 * Dn];
__device__ __half g_WoT  [Dn * Dn];
__device__ __half g_W1T  [FFn * Dn];
__device__ __half g_W2T  [Dn * FFn];
__device__ __half g_xh  [(size_t)Mn * Dn];     // fp16 copy of x
__device__ __half g_QKVh[(size_t)Mn * 3 * Dn]; // q|k|v per row (fp16)
__device__ __half g_Vth [(size_t)64 * HDn * Sn]; // V transposed: [bh][hd][s]
__device__ __half g_Oh  [(size_t)Mn * Dn];     // attention out (fp16)
__device__ float  g_T   [(size_t)Mn * Dn];     // residual temp
__device__ float  g_Hh  [(size_t)Mn * Dn];     // post-LN1 hidden (fp32)
__device__ __half g_Hhh [(size_t)Mn * Dn];     // post-LN1 hidden (fp16)
__device__ __half g_FFh [(size_t)Mn * FFn];    // FFN intermediate (fp16)

// ---------------- helpers ----------------
__device__ __forceinline__ uint32_t smem_u32(const void* p) {
    return (uint32_t)__cvta_generic_to_shared(p);
}
__device__ __forceinline__ void cpasync16(uint32_t dst, const void* src) {
    asm volatile("cp.async.ca.shared.global [%0], [%1], 16;" :: "r"(dst), "l"(src) : "memory");
}
__device__ __forceinline__ void cp_commit() {
    asm volatile("cp.async.commit_group;" ::: "memory");
}
__device__ __forceinline__ void mma_f16(float* c, const uint32_t* a, const uint32_t* b) {
    asm volatile(
        "mma.sync.aligned.m16n8k16.row.col.f32.f16.f16.f32 "
        "{%0,%1,%2,%3}, {%4,%5,%6,%7}, {%8,%9}, {%0,%1,%2,%3};"
        : "+f"(c[0]), "+f"(c[1]), "+f"(c[2]), "+f"(c[3])
        : "r"(a[0]), "r"(a[1]), "r"(a[2]), "r"(a[3]), "r"(b[0]), "r"(b[1]));
}
__device__ __forceinline__ void ldsm_x4(uint32_t* r, uint32_t addr) {
    asm volatile("ldmatrix.sync.aligned.m8n8.x4.shared.b16 {%0,%1,%2,%3}, [%4];"
                 : "=r"(r[0]), "=r"(r[1]), "=r"(r[2]), "=r"(r[3]) : "r"(addr));
}

// ---------------- weight/activation repacks ----------------
__global__ void repack_qkvT(const float* __restrict__ wq, const float* __restrict__ wk,
                            const float* __restrict__ wv, const float* __restrict__ bq,
                            const float* __restrict__ bk, const float* __restrict__ bv) {
    int gid = blockIdx.x * blockDim.x + threadIdx.x;
    if (gid < 3 * Dn * Dn) {
        int n = gid >> 10;
        int d = gid & 1023;
        int which = n >> 10;
        int c = n & 1023;
        int h = c >> 6, f = c & 63;
        const float* w = (which == 0) ? wq : (which == 1) ? wk : wv;
        g_WqkvT[gid] = __float2half(w[((size_t)h * Dn + d) * HDn + f]);
    }
    if (gid < 3 * Dn) {
        int which = gid >> 10; int c = gid & 1023;
        const float* b = (which == 0) ? bq : (which == 1) ? bk : bv;
        g_Bqkv[gid] = b[c];
    }
}

__global__ void transpose_kh(__half* __restrict__ dst, const float* __restrict__ src,
                             int R, int C) {
    __shared__ float tile[32][33];
    int c0 = blockIdx.x * 32, r0 = blockIdx.y * 32;
    int tx = threadIdx.x, ty = threadIdx.y;
    #pragma unroll
    for (int i = 0; i < 32; i += 8)
        tile[ty + i][tx] = src[(size_t)(r0 + ty + i) * C + c0 + tx];
    __syncthreads();
    #pragma unroll
    for (int i = 0; i < 32; i += 8)
        dst[(size_t)(c0 + ty + i) * R + r0 + tx] = __float2half(tile[tx][ty + i]);
}

__global__ void f2h(const float* __restrict__ X, __half* __restrict__ Y, int n4) {
    int i = blockIdx.x * blockDim.x + threadIdx.x;
    if (i < n4) {
        float4 v = *(const float4*)(X + (size_t)i * 4);
        __half2 h0 = __floats2half2_rn(v.x, v.y);
        __half2 h1 = __floats2half2_rn(v.z, v.w);
        *(uint2*)(Y + (size_t)i * 4) = make_uint2(*(uint32_t*)&h0, *(uint32_t*)&h1);
    }
}

// V per-head transpose: Vth[(bh*64 + f)*S + s] = QKVh[(b*S+s)*3072 + 2048 + h*64 + f]
__global__ void vtrans(const __half* __restrict__ QKVh, __half* __restrict__ Vth) {
    __shared__ __half tile[32][33];
    int bh = blockIdx.z, b = bh >> 4, h = bh & 15;
    int s0 = blockIdx.x * 32, f0 = blockIdx.y * 32;
    int tx = threadIdx.x, ty = threadIdx.y;
    #pragma unroll
    for (int i = 0; i < 32; i += 8)
        tile[ty + i][tx] = QKVh[(size_t)(b * Sn + s0 + ty + i) * 3072 + 2048 + h * 64 + f0 + tx];
    __syncthreads();
    #pragma unroll
    for (int i = 0; i < 32; i += 8)
        Vth[((size_t)bh * 64 + f0 + ty + i) * Sn + s0 + tx] = tile[tx][ty + i];
}

// ---------------- fp16 tensor GEMM 128x128x32, cp.async double buffer --------
// (R8 proven config) 128 threads = 4 warps (2m x 2n); warp tile 64x64.
// SMEM rows of 40 halves -> conflict-free for cp.async STS and LDSM.
enum { EPI_BIAS = 0, EPI_GELUH = 1, EPI_RES = 2, EPI_BIASH = 3 };

__device__ __forceinline__ float gelu_f(float x) {
    return 0.5f * x * (1.0f + erff(x * 0.70710678118654752440f));
}

constexpr int ASTRH = 40;   // smem row stride in halves

template <int EPI>
__global__ void __launch_bounds__(128, 2)
hgemm(const __half* __restrict__ A, const __half* __restrict__ Bt,
      const float* __restrict__ bias, const float* __restrict__ Res,
      float* __restrict__ C, __half* __restrict__ Ch, int M, int N, int K) {
    __shared__ __half As[2][128 * ASTRH];
    __shared__ __half Bs[2][128 * ASTRH];

    const int tid  = threadIdx.x;
    const int lane = tid & 31, wid = tid >> 5;
    const int quad = lane >> 2, qt = lane & 3;
    const int wm = wid & 1, wn = wid >> 1;
    const int m0 = blockIdx.y * 128, n0 = blockIdx.x * 128;

    const uint32_t aS0 = smem_u32(As[0]), aS1 = smem_u32(As[1]);
    const uint32_t bS0 = smem_u32(Bs[0]), bS1 = smem_u32(Bs[1]);

    const int rL = tid >> 2;
    const int kc = (tid & 3) * 8;

    // LDSM per-thread address offsets (bytes) within a stage buffer.
    uint32_t aOff[4], bOff[4];
    {
        const int ar = (lane & 7) + ((lane >> 3) & 1) * 8;
        const int ak = (lane >> 4) * 8;
        #pragma unroll
        for (int mt = 0; mt < 4; mt++)
            aOff[mt] = ((wm * 64 + mt * 16 + ar) * ASTRH + ak) * 2;
        const int br = (lane & 7) + ((lane >> 4) & 1) * 8;
        const int bk = ((lane >> 3) & 1) * 8;
        #pragma unroll
        for (int np = 0; np < 4; np++)
            bOff[np] = ((wn * 64 + np * 16 + br) * ASTRH + bk) * 2;
    }

    float acc[4][8][4] = {};

    auto load_tile = [&](int kt, int buf) {
        const uint32_t aB = (buf ? aS1 : aS0);
        const uint32_t bB = (buf ? bS1 : bS0);
        const __half* Ap = A  + (size_t)m0 * K + (size_t)kt * 32 + kc;
        const __half* Bp = Bt + (size_t)n0 * K + (size_t)kt * 32 + kc;
        #pragma unroll
        for (int i = 0; i < 4; i++) {
            int row = rL + i * 32;
            uint32_t off = row * (ASTRH * 2) + kc * 2;
            cpasync16(aB + off, Ap + (size_t)row * K);
            cpasync16(bB + off, Bp + (size_t)row * K);
        }
        cp_commit();
    };

    const int NT = K >> 5;
    load_tile(0, 0);

    for (int kt = 0; kt < NT; kt++) {
        const int buf = kt & 1;
        if (kt + 1 < NT) {
            load_tile(kt + 1, buf ^ 1);
            asm volatile("cp.async.wait_group 1;" ::: "memory");
        } else {
            asm volatile("cp.async.wait_group 0;" ::: "memory");
        }
        __syncthreads();

        const uint32_t AbU = (buf ? aS1 : aS0);
        const uint32_t BbU = (buf ? bS1 : bS0);
        #pragma unroll
        for (int ks = 0; ks < 2; ks++) {
            const uint32_t kbB = ks * 16 * 2;
            uint32_t af[4][4], bf4[4][4];
            #pragma unroll
            for (int mt = 0; mt < 4; mt++)
                ldsm_x4(af[mt], AbU + aOff[mt] + kbB);
            #pragma unroll
            for (int np = 0; np < 4; np++)
                ldsm_x4(bf4[np], BbU + bOff[np] + kbB);
            #pragma unroll
            for (int mt = 0; mt < 4; mt++)
                #pragma unroll
                for (int nt = 0; nt < 8; nt++)
                    mma_f16(acc[mt][nt], af[mt], &bf4[nt >> 1][(nt & 1) * 2]);
        }
        __syncthreads();
    }

    #pragma unroll
    for (int mt = 0; mt < 4; mt++) {
        const int r0 = m0 + wm * 64 + mt * 16 + quad;
        #pragma unroll
        for (int nt = 0; nt < 8; nt++) {
            const int col = n0 + wn * 64 + nt * 8 + qt * 2;
            const float2 bv2 = *(const float2*)&bias[col];
            #pragma unroll
            for (int half = 0; half < 2; half++) {
                const int r = r0 + half * 8;
                float2 y;
                y.x = acc[mt][nt][half * 2 + 0] + bv2.x;
                y.y = acc[mt][nt][half * 2 + 1] + bv2.y;
                size_t base = (size_t)r * N + col;
                if (EPI == EPI_GELUH) {
                    y.x = gelu_f(y.x); y.y = gelu_f(y.y);
                    __half2 hh = __floats2half2_rn(y.x, y.y);
                    *(__half2*)&Ch[base] = hh;
                } else if (EPI == EPI_BIASH) {
                    __half2 hh = __floats2half2_rn(y.x, y.y);
                    *(__half2*)&Ch[base] = hh;
                } else if (EPI == EPI_RES) {
                    float2 rr = *(const float2*)&Res[base];
                    y.x += rr.x; y.y += rr.y;
                    *(float2*)&C[base] = y;
                } else {
                    *(float2*)&C[base] = y;
                }
            }
        }
    }
}

// ---------------- tensor-core causal flash attention v2 ----------------------
// 256 threads = 8 warps; CTA = 128 query rows x one (b,h); warp = 16 rows.
// K/V tiles of 64 keys double-buffered; LDSM fragments; causal warp-skip.
constexpr int FSTR = 72;
constexpr int FA_Q_H  = 128 * FSTR;               // 9216
constexpr int FA_KV_H = 64 * FSTR;                // 4608
constexpr int FA_SMEM = (FA_Q_H + 4 * FA_KV_H) * 2;   // 55296 B

__global__ void __launch_bounds__(256, 2)
fattn(const __half* __restrict__ QKVh, const __half* __restrict__ Vth,
      __half* __restrict__ O) {
    extern __shared__ __half fs[];
    const uint32_t sB = smem_u32(fs);
    // halves layout: Q @0, K0 @9216, K1 @13824, V0 @18432, V1 @23040

    const int tid = threadIdx.x;
    const int lane = tid & 31, wid = tid >> 5;
    const int q4 = lane >> 2, qt2 = (lane & 3) * 2;
    const int qtile = gridDim.x - 1 - blockIdx.x;    // big tiles first
    const int bh = blockIdx.y, b = bh >> 4, h = bh & 15;
    const int r0 = qtile * 128;

    const int ar = (lane & 7) + ((lane >> 3) & 1) * 8;
    const int ak = (lane >> 4) * 8;
    const int br = (lane & 7) + ((lane >> 4) & 1) * 8;
    const int bk = ((lane >> 3) & 1) * 8;

    // load Q (128 rows x 64 halves)
    {
        const __half* Qg = QKVh + ((size_t)(b * Sn + r0)) * 3072 + h * 64;
        #pragma unroll
        for (int i = 0; i < 4; i++) {
            int id = tid + i * 256;          // 0..1023
            int row = id >> 3, c = (id & 7) * 8;
            cpasync16(sB + (row * FSTR + c) * 2, Qg + (size_t)row * 3072 + c);
        }
        cp_commit();
    }

    auto loadKV = [&](int kt, int buf) {
        const __half* Kg = QKVh + ((size_t)(b * Sn + kt * 64)) * 3072 + 1024 + h * 64;
        const __half* Vg = Vth + ((size_t)bh * 64) * Sn + kt * 64;
        const uint32_t kB = sB + (FA_Q_H + buf * FA_KV_H) * 2;
        const uint32_t vB = sB + (FA_Q_H + (2 + buf) * FA_KV_H) * 2;
        #pragma unroll
        for (int i = 0; i < 2; i++) {
            int id = tid + i * 256;          // 0..511
            int row = id >> 3, c = (id & 7) * 8;
            cpasync16(kB + (row * FSTR + c) * 2, Kg + (size_t)row * 3072 + c);
            cpasync16(vB + (row * FSTR + c) * 2, Vg + (size_t)row * Sn + c);
        }
        cp_commit();
    };

    loadKV(0, 0);

    asm volatile("cp.async.wait_group 1;" ::: "memory");   // Q ready
    __syncthreads();
    uint32_t aQ[4][4];
    #pragma unroll
    for (int kcc = 0; kcc < 4; kcc++)
        ldsm_x4(aQ[kcc], sB + ((wid * 16 + ar) * FSTR + kcc * 16 + ak) * 2);

    const int rowg0 = r0 + wid * 16 + q4;
    const int rowg1 = rowg0 + 8;
    const int wrow_max = r0 + wid * 16 + 15;

    float m0 = NEG_INF, m1 = NEG_INF, l0 = 0.f, l1 = 0.f;
    float o[8][4] = {};

    const int ntk = 2 * qtile + 2;
    for (int kt = 0; kt < ntk; kt++) {
        const int buf = kt & 1;
        if (kt + 1 < ntk) {
            loadKV(kt + 1, buf ^ 1);
            asm volatile("cp.async.wait_group 1;" ::: "memory");
        } else {
            asm volatile("cp.async.wait_group 0;" ::: "memory");
        }
        __syncthreads();

        const int gk0 = kt * 64;
        if (gk0 <= wrow_max) {
            const uint32_t kB = sB + (FA_Q_H + buf * FA_KV_H) * 2;
            const uint32_t vB = sB + (FA_Q_H + (2 + buf) * FA_KV_H) * 2;

            float s[8][4] = {};
            #pragma unroll
            for (int kcc = 0; kcc < 4; kcc++) {
                uint32_t bf4[4][4];
                #pragma unroll
                for (int np = 0; np < 4; np++)
                    ldsm_x4(bf4[np], kB + ((np * 16 + br) * FSTR + kcc * 16 + bk) * 2);
                #pragma unroll
                for (int nt = 0; nt < 8; nt++)
                    mma_f16(s[nt], aQ[kcc], &bf4[nt >> 1][(nt & 1) * 2]);
            }

            const int colb = gk0 + qt2;
            float mx0 = NEG_INF, mx1 = NEG_INF;
            #pragma unroll
            for (int nt = 0; nt < 8; nt++) {
                const int c0 = colb + nt * 8;
                s[nt][0] = (c0     <= rowg0) ? s[nt][0] * 0.125f : NEG_INF;
                s[nt][1] = (c0 + 1 <= rowg0) ? s[nt][1] * 0.125f : NEG_INF;
                s[nt][2] = (c0     <= rowg1) ? s[nt][2] * 0.125f : NEG_INF;
                s[nt][3] = (c0 + 1 <= rowg1) ? s[nt][3] * 0.125f : NEG_INF;
                mx0 = fmaxf(mx0, fmaxf(s[nt][0], s[nt][1]));
                mx1 = fmaxf(mx1, fmaxf(s[nt][2], s[nt][3]));
            }
            mx0 = fmaxf(mx0, __shfl_xor_sync(0xffffffffu, mx0, 1));
            mx0 = fmaxf(mx0, __shfl_xor_sync(0xffffffffu, mx0, 2));
            mx1 = fmaxf(mx1, __shfl_xor_sync(0xffffffffu, mx1, 1));
            mx1 = fmaxf(mx1, __shfl_xor_sync(0xffffffffu, mx1, 2));

            const float mn0 = fmaxf(m0, mx0), mn1 = fmaxf(m1, mx1);
            const float sc0 = __expf(m0 - mn0), sc1 = __expf(m1 - mn1);
            m0 = mn0; m1 = mn1;

            float rs0 = 0.f, rs1 = 0.f;
            uint32_t pf[4][4];
            #pragma unroll
            for (int nt = 0; nt < 8; nt++) {
                float p0 = __expf(s[nt][0] - m0);
                float p1 = __expf(s[nt][1] - m0);
                float p2 = __expf(s[nt][2] - m1);
                float p3 = __expf(s[nt][3] - m1);
                rs0 += p0 + p1; rs1 += p2 + p3;
                __half2 h01 = __floats2half2_rn(p0, p1);
                __half2 h23 = __floats2half2_rn(p2, p3);
                pf[nt >> 1][(nt & 1) * 2 + 0] = *(uint32_t*)&h01;
                pf[nt >> 1][(nt & 1) * 2 + 1] = *(uint32_t*)&h23;
            }
            rs0 += __shfl_xor_sync(0xffffffffu, rs0, 1);
            rs0 += __shfl_xor_sync(0xffffffffu, rs0, 2);
            rs1 += __shfl_xor_sync(0xffffffffu, rs1, 1);
            rs1 += __shfl_xor_sync(0xffffffffu, rs1, 2);
            l0 = l0 * sc0 + rs0;
            l1 = l1 * sc1 + rs1;

            #pragma unroll
            for (int nt = 0; nt < 8; nt++) {
                o[nt][0] *= sc0; o[nt][1] *= sc0;
                o[nt][2] *= sc1; o[nt][3] *= sc1;
            }

            #pragma unroll
            for (int kcc = 0; kcc < 4; kcc++) {
                uint32_t bf4[4][4];
                #pragma unroll
                for (int np = 0; np < 4; np++)
                    ldsm_x4(bf4[np], vB + ((np * 16 + br) * FSTR + kcc * 16 + bk) * 2);
                #pragma unroll
                for (int nt = 0; nt < 8; nt++)
                    mma_f16(o[nt], pf[kcc], &bf4[nt >> 1][(nt & 1) * 2]);
            }
        }
        __syncthreads();
    }

    const float li0 = 1.0f / l0, li1 = 1.0f / l1;
    __half* Op0 = O + ((size_t)(b * Sn + rowg0)) * Dn + h * 64 + qt2;
    __half* Op1 = O + ((size_t)(b * Sn + rowg1)) * Dn + h * 64 + qt2;
    #pragma unroll
    for (int nt = 0; nt < 8; nt++) {
        __half2 h0 = __floats2half2_rn(o[nt][0] * li0, o[nt][1] * li0);
        __half2 h1 = __floats2half2_rn(o[nt][2] * li1, o[nt][3] * li1);
        *(__half2*)(Op0 + nt * 8) = h0;
        *(__half2*)(Op1 + nt * 8) = h1;
    }
}

// ---------------- LayerNorm: one block per row of 1024 -----------------------
__global__ void __launch_bounds__(256)
ln_kernel(const float* __restrict__ X, const float* __restrict__ G,
          const float* __restrict__ Bt, float* __restrict__ Y,
          __half* __restrict__ Yh) {
    const int row = blockIdx.x;
    const int t = threadIdx.x;
    const float* x = X + (size_t)row * Dn;

    float4 v = *(const float4*)(x + t * 4);
    float s  = v.x + v.y + v.z + v.w;
    float sq = v.x * v.x + v.y * v.y + v.z * v.z + v.w * v.w;
    #pragma unroll
    for (int off = 16; off; off >>= 1) {
        s  += __shfl_xor_sync(0xffffffffu, s,  off);
        sq += __shfl_xor_sync(0xffffffffu, sq, off);
    }
    __shared__ float rs[8], rq[8];
    int wid = t >> 5, lane = t & 31;
    if (lane == 0) { rs[wid] = s; rq[wid] = sq; }
    __syncthreads();
    if (t == 0) {
        float S = 0.f, Q = 0.f;
        #pragma unroll
        for (int i = 0; i < 8; i++) { S += rs[i]; Q += rq[i]; }
        float mean = S * (1.0f / Dn);
        float var  = Q * (1.0f / Dn) - mean * mean;
        rs[0] = mean;
        rq[0] = rsqrtf(var + 1e-5f);
    }
    __syncthreads();
    const float mean = rs[0], rstd = rq[0];

    float4 gv = *(const float4*)(G + t * 4);
    float4 bv = *(const float4*)(Bt + t * 4);
    float4 y;
    y.x = (v.x - mean) * rstd * gv.x + bv.x;
    y.y = (v.y - mean) * rstd * gv.y + bv.y;
    y.z = (v.z - mean) * rstd * gv.z + bv.z;
    y.w = (v.w - mean) * rstd * gv.w + bv.w;
    *(float4*)(Y + (size_t)row * Dn + t * 4) = y;
    if (Yh) {
        __half2 h0 = __floats2half2_rn(y.x, y.y);
        __half2 h1 = __floats2half2_rn(y.z, y.w);
        *(uint2*)(Yh + (size_t)row * Dn + t * 4) =
            make_uint2(*(uint32_t*)&h0, *(uint32_t*)&h1);
    }
}

// ---------------- launch ----------------
extern "C" void kernel_launch(void* const* d_in, const int* in_sizes, int n_in,
                              void* d_out, int out_size) {
    const float* x   = (const float*)d_in[0];
    const float* wq  = (const float*)d_in[1];
    const float* bq  = (const float*)d_in[2];
    const float* wk  = (const float*)d_in[3];
    const float* bk  = (const float*)d_in[4];
    const float* wv  = (const float*)d_in[5];
    const float* bv  = (const float*)d_in[6];
    const float* wo  = (const float*)d_in[7];
    const float* bo  = (const float*)d_in[8];
    const float* w1  = (const float*)d_in[9];
    const float* b1  = (const float*)d_in[10];
    const float* w2  = (const float*)d_in[11];
    const float* b2  = (const float*)d_in[12];
    const float* g1  = (const float*)d_in[13];
    const float* be1 = (const float*)d_in[14];
    const float* g2  = (const float*)d_in[15];
    const float* be2 = (const float*)d_in[16];

    __half *WqkvT, *WoT, *W1T, *W2T, *xh, *QKVh, *Vth, *Oh, *Hhh, *FFh;
    float *Bqkv, *T, *Hh;
    cudaGetSymbolAddress((void**)&WqkvT, g_WqkvT);
    cudaGetSymbolAddress((void**)&Bqkv,  g_Bqkv);
    cudaGetSymbolAddress((void**)&WoT,   g_WoT);
    cudaGetSymbolAddress((void**)&W1T,   g_W1T);
    cudaGetSymbolAddress((void**)&W2T,   g_W2T);
    cudaGetSymbolAddress((void**)&xh,    g_xh);
    cudaGetSymbolAddress((void**)&QKVh,  g_QKVh);
    cudaGetSymbolAddress((void**)&Vth,   g_Vth);
    cudaGetSymbolAddress((void**)&Oh,    g_Oh);
    cudaGetSymbolAddress((void**)&T,     g_T);
    cudaGetSymbolAddress((void**)&Hh,    g_Hh);
    cudaGetSymbolAddress((void**)&Hhh,   g_Hhh);
    cudaGetSymbolAddress((void**)&FFh,   g_FFh);

    cudaFuncSetAttribute(fattn, cudaFuncAttributeMaxDynamicSharedMemorySize, FA_SMEM);

    // 0) weight repacks + x -> fp16
    repack_qkvT<<<(3 * Dn * Dn + 255) / 256, 256>>>(wq, wk, wv, bq, bk, bv);
    transpose_kh<<<dim3(Dn / 32, Dn / 32),  dim3(32, 8)>>>(WoT, wo, Dn, Dn);
    transpose_kh<<<dim3(FFn / 32, Dn / 32), dim3(32, 8)>>>(W1T, w1, Dn, FFn);
    transpose_kh<<<dim3(Dn / 32, FFn / 32), dim3(32, 8)>>>(W2T, w2, FFn, Dn);
    f2h<<<(Mn * Dn / 4 + 255) / 256, 256>>>(x, xh, Mn * Dn / 4);

    // 1) QKV projection -> fp16
    hgemm<EPI_BIASH><<<dim3(3 * Dn / 128, Mn / 128), 128>>>(
        xh, WqkvT, Bqkv, nullptr, nullptr, QKVh, Mn, 3 * Dn, Dn);
    // 1b) V transpose per head
    vtrans<<<dim3(Sn / 32, HDn / 32, 64), dim3(32, 8)>>>(QKVh, Vth);
    // 2) tensor-core causal flash attention -> Oh (fp16)
    fattn<<<dim3(Sn / 128, 64), 256, FA_SMEM>>>(QKVh, Vth, Oh);
    // 3) O projection + residual x
    hgemm<EPI_RES><<<dim3(Dn / 128, Mn / 128), 128>>>(
        Oh, WoT, bo, x, T, nullptr, Mn, Dn, Dn);
    // 4) LayerNorm 1 (fp32 + fp16 twin)
    ln_kernel<<<Mn, 256>>>(T, g1, be1, Hh, Hhh);
    // 5) FFN up + exact GELU -> fp16
    hgemm<EPI_GELUH><<<dim3(FFn / 128, Mn / 128), 128>>>(
        Hhh, W1T, b1, nullptr, nullptr, FFh, Mn, FFn, Dn);
    // 6) FFN down + residual Hh
    hgemm<EPI_RES><<<dim3(Dn / 128, Mn / 128), 128>>>(
        FFh, W2T, b2, Hh, T, nullptr, Mn, Dn, FFn);
    // 7) LayerNorm 2 -> output
    ln_kernel<<<Mn, 256>>>(T, g2, be2, (float*)d_out, nullptr);
}

// round 11
// speedup vs baseline: 1.0584x; 1.0327x over previous
#include <cuda_runtime.h>
#include <cuda_fp16.h>
#include <math.h>
#include <stdint.h>

// Problem constants
constexpr int Bn  = 4;
constexpr int Sn  = 2048;
constexpr int Dn  = 1024;
constexpr int HDn = 64;
constexpr int FFn = 4096;
constexpr int Mn  = Bn * Sn;        // 8192 rows
constexpr float NEG_INF = -1.0e30f;

// ---------------- scratch (static __device__, no allocations) ----------------
__device__ __half g_WqkvT[3 * Dn * Dn];        // [N=3072][K=1024] K-major, fp16
__device__ float  g_Bqkv [3 * Dn];
__device__ __half g_WoT  [Dn * Dn];
__device__ __half g_W1T  [FFn * Dn];
__device__ __half g_W2T  [Dn * FFn];
__device__ __half g_xh  [(size_t)Mn * Dn];     // fp16 copy of x
__device__ __half g_QKVh[(size_t)Mn * 3 * Dn]; // q|k|v per row (fp16)
__device__ __half g_Vth [(size_t)64 * HDn * Sn]; // V transposed: [bh][hd][s]
__device__ __half g_Oh  [(size_t)Mn * Dn];     // attention out (fp16)
__device__ float  g_T   [(size_t)Mn * Dn];     // residual temp
__device__ float  g_Hh  [(size_t)Mn * Dn];     // post-LN1 hidden (fp32)
__device__ __half g_Hhh [(size_t)Mn * Dn];     // post-LN1 hidden (fp16)
__device__ __half g_FFh [(size_t)Mn * FFn];    // FFN intermediate (fp16)

// ---------------- helpers ----------------
__device__ __forceinline__ uint32_t smem_u32(const void* p) {
    return (uint32_t)__cvta_generic_to_shared(p);
}
__device__ __forceinline__ void cpasync16(uint32_t dst, const void* src) {
    asm volatile("cp.async.ca.shared.global [%0], [%1], 16;" :: "r"(dst), "l"(src) : "memory");
}
__device__ __forceinline__ void cp_commit() {
    asm volatile("cp.async.commit_group;" ::: "memory");
}
__device__ __forceinline__ void mma_f16(float* c, const uint32_t* a, const uint32_t* b) {
    asm volatile(
        "mma.sync.aligned.m16n8k16.row.col.f32.f16.f16.f32 "
        "{%0,%1,%2,%3}, {%4,%5,%6,%7}, {%8,%9}, {%0,%1,%2,%3};"
        : "+f"(c[0]), "+f"(c[1]), "+f"(c[2]), "+f"(c[3])
        : "r"(a[0]), "r"(a[1]), "r"(a[2]), "r"(a[3]), "r"(b[0]), "r"(b[1]));
}
__device__ __forceinline__ void ldsm_x4(uint32_t* r, uint32_t addr) {
    asm volatile("ldmatrix.sync.aligned.m8n8.x4.shared.b16 {%0,%1,%2,%3}, [%4];"
                 : "=r"(r[0]), "=r"(r[1]), "=r"(r[2]), "=r"(r[3]) : "r"(addr));
}

// ---------------- weight/activation repacks ----------------
__global__ void repack_qkvT(const float* __restrict__ wq, const float* __restrict__ wk,
                            const float* __restrict__ wv, const float* __restrict__ bq,
                            const float* __restrict__ bk, const float* __restrict__ bv) {
    int gid = blockIdx.x * blockDim.x + threadIdx.x;
    if (gid < 3 * Dn * Dn) {
        int n = gid >> 10;
        int d = gid & 1023;
        int which = n >> 10;
        int c = n & 1023;
        int h = c >> 6, f = c & 63;
        const float* w = (which == 0) ? wq : (which == 1) ? wk : wv;
        g_WqkvT[gid] = __float2half(w[((size_t)h * Dn + d) * HDn + f]);
    }
    if (gid < 3 * Dn) {
        int which = gid >> 10; int c = gid & 1023;
        const float* b = (which == 0) ? bq : (which == 1) ? bk : bv;
        g_Bqkv[gid] = b[c];
    }
}

__global__ void transpose_kh(__half* __restrict__ dst, const float* __restrict__ src,
                             int R, int C) {
    __shared__ float tile[32][33];
    int c0 = blockIdx.x * 32, r0 = blockIdx.y * 32;
    int tx = threadIdx.x, ty = threadIdx.y;
    #pragma unroll
    for (int i = 0; i < 32; i += 8)
        tile[ty + i][tx] = src[(size_t)(r0 + ty + i) * C + c0 + tx];
    __syncthreads();
    #pragma unroll
    for (int i = 0; i < 32; i += 8)
        dst[(size_t)(c0 + ty + i) * R + r0 + tx] = __float2half(tile[tx][ty + i]);
}

__global__ void f2h(const float* __restrict__ X, __half* __restrict__ Y, int n4) {
    int i = blockIdx.x * blockDim.x + threadIdx.x;
    if (i < n4) {
        float4 v = *(const float4*)(X + (size_t)i * 4);
        __half2 h0 = __floats2half2_rn(v.x, v.y);
        __half2 h1 = __floats2half2_rn(v.z, v.w);
        *(uint2*)(Y + (size_t)i * 4) = make_uint2(*(uint32_t*)&h0, *(uint32_t*)&h1);
    }
}

// V per-head transpose: Vth[(bh*64 + f)*S + s] = QKVh[(b*S+s)*3072 + 2048 + h*64 + f]
__global__ void vtrans(const __half* __restrict__ QKVh, __half* __restrict__ Vth) {
    __shared__ __half tile[32][33];
    int bh = blockIdx.z, b = bh >> 4, h = bh & 15;
    int s0 = blockIdx.x * 32, f0 = blockIdx.y * 32;
    int tx = threadIdx.x, ty = threadIdx.y;
    #pragma unroll
    for (int i = 0; i < 32; i += 8)
        tile[ty + i][tx] = QKVh[(size_t)(b * Sn + s0 + ty + i) * 3072 + 2048 + h * 64 + f0 + tx];
    __syncthreads();
    #pragma unroll
    for (int i = 0; i < 32; i += 8)
        Vth[((size_t)bh * 64 + f0 + ty + i) * Sn + s0 + tx] = tile[tx][ty + i];
}

// ---------------- fp16 tensor GEMM 128x128x32, 3-stage cp.async --------------
// 128 threads = 4 warps (2m x 2n); warp tile 64x64; 2 CTAs/SM.
// 3 stages -> iter kt writes stage (kt+2)%3, last read at iter kt-1, so ONE
// __syncthreads per k-iter suffices. SMEM rows of 40 halves (conflict-free).
enum { EPI_BIAS = 0, EPI_GELUH = 1, EPI_RES = 2, EPI_BIASH = 3 };

__device__ __forceinline__ float gelu_f(float x) {
    return 0.5f * x * (1.0f + erff(x * 0.70710678118654752440f));
}

constexpr int ASTRH = 40;                     // smem row stride in halves
constexpr int G3_A_H  = 128 * ASTRH;          // 5120 halves per matrix
constexpr int G3_STG_H = 2 * G3_A_H;          // 10240 halves per stage (A+B)
constexpr int GEMM_SMEM = 3 * G3_STG_H * 2;   // 61440 B

template <int EPI>
__global__ void __launch_bounds__(128, 2)
hgemm(const __half* __restrict__ A, const __half* __restrict__ Bt,
      const float* __restrict__ bias, const float* __restrict__ Res,
      float* __restrict__ C, __half* __restrict__ Ch, int M, int N, int K) {
    extern __shared__ __half sh[];
    const uint32_t sB = smem_u32(sh);

    const int tid  = threadIdx.x;
    const int lane = tid & 31, wid = tid >> 5;
    const int quad = lane >> 2, qt = lane & 3;
    const int wm = wid & 1, wn = wid >> 1;
    const int m0 = blockIdx.y * 128, n0 = blockIdx.x * 128;

    const int rL = tid >> 2;
    const int kc = (tid & 3) * 8;

    // LDSM per-thread address offsets (bytes) within a stage buffer.
    uint32_t aOff[4], bOff[4];
    {
        const int ar = (lane & 7) + ((lane >> 3) & 1) * 8;
        const int ak = (lane >> 4) * 8;
        #pragma unroll
        for (int mt = 0; mt < 4; mt++)
            aOff[mt] = ((wm * 64 + mt * 16 + ar) * ASTRH + ak) * 2;
        const int br = (lane & 7) + ((lane >> 4) & 1) * 8;
        const int bk = ((lane >> 3) & 1) * 8;
        #pragma unroll
        for (int np = 0; np < 4; np++)
            bOff[np] = ((wn * 64 + np * 16 + br) * ASTRH + bk) * 2;
    }

    float acc[4][8][4] = {};

    auto load_tile = [&](int kt, int s) {
        const uint32_t aB = sB + s * (G3_STG_H * 2);
        const uint32_t bB = aB + G3_A_H * 2;
        const __half* Ap = A  + (size_t)m0 * K + (size_t)kt * 32 + kc;
        const __half* Bp = Bt + (size_t)n0 * K + (size_t)kt * 32 + kc;
        #pragma unroll
        for (int i = 0; i < 4; i++) {
            int row = rL + i * 32;
            uint32_t off = row * (ASTRH * 2) + kc * 2;
            cpasync16(aB + off, Ap + (size_t)row * K);
            cpasync16(bB + off, Bp + (size_t)row * K);
        }
        cp_commit();
    };

    const int NT = K >> 5;
    load_tile(0, 0);
    load_tile(1, 1);

    for (int kt = 0; kt < NT; kt++) {
        asm volatile("cp.async.wait_group 1;" ::: "memory");  // stage kt ready
        __syncthreads();                                      // iter kt-1 reads done
        if (kt + 2 < NT) load_tile(kt + 2, (kt + 2) % 3);
        else             cp_commit();                         // keep group order

        const uint32_t AbU = sB + (kt % 3) * (G3_STG_H * 2);
        const uint32_t BbU = AbU + G3_A_H * 2;
        #pragma unroll
        for (int ks = 0; ks < 2; ks++) {
            const uint32_t kbB = ks * 16 * 2;
            uint32_t af[4][4], bf4[4][4];
            #pragma unroll
            for (int mt = 0; mt < 4; mt++)
                ldsm_x4(af[mt], AbU + aOff[mt] + kbB);
            #pragma unroll
            for (int np = 0; np < 4; np++)
                ldsm_x4(bf4[np], BbU + bOff[np] + kbB);
            #pragma unroll
            for (int mt = 0; mt < 4; mt++)
                #pragma unroll
                for (int nt = 0; nt < 8; nt++)
                    mma_f16(acc[mt][nt], af[mt], &bf4[nt >> 1][(nt & 1) * 2]);
        }
    }

    #pragma unroll
    for (int mt = 0; mt < 4; mt++) {
        const int r0 = m0 + wm * 64 + mt * 16 + quad;
        #pragma unroll
        for (int nt = 0; nt < 8; nt++) {
            const int col = n0 + wn * 64 + nt * 8 + qt * 2;
            const float2 bv2 = *(const float2*)&bias[col];
            #pragma unroll
            for (int half = 0; half < 2; half++) {
                const int r = r0 + half * 8;
                float2 y;
                y.x = acc[mt][nt][half * 2 + 0] + bv2.x;
                y.y = acc[mt][nt][half * 2 + 1] + bv2.y;
                size_t base = (size_t)r * N + col;
                if (EPI == EPI_GELUH) {
                    y.x = gelu_f(y.x); y.y = gelu_f(y.y);
                    __half2 hh = __floats2half2_rn(y.x, y.y);
                    *(__half2*)&Ch[base] = hh;
                } else if (EPI == EPI_BIASH) {
                    __half2 hh = __floats2half2_rn(y.x, y.y);
                    *(__half2*)&Ch[base] = hh;
                } else if (EPI == EPI_RES) {
                    float2 rr = *(const float2*)&Res[base];
                    y.x += rr.x; y.y += rr.y;
                    *(float2*)&C[base] = y;
                } else {
                    *(float2*)&C[base] = y;
                }
            }
        }
    }
}

// ---------------- tensor-core causal flash attention v2 ----------------------
// 256 threads = 8 warps; CTA = 128 query rows x one (b,h); warp = 16 rows.
// K/V tiles of 64 keys double-buffered; LDSM fragments; causal warp-skip.
constexpr int FSTR = 72;
constexpr int FA_Q_H  = 128 * FSTR;               // 9216
constexpr int FA_KV_H = 64 * FSTR;                // 4608
constexpr int FA_SMEM = (FA_Q_H + 4 * FA_KV_H) * 2;   // 55296 B

__global__ void __launch_bounds__(256, 2)
fattn(const __half* __restrict__ QKVh, const __half* __restrict__ Vth,
      __half* __restrict__ O) {
    extern __shared__ __half fs[];
    const uint32_t sB = smem_u32(fs);
    // halves layout: Q @0, K0 @9216, K1 @13824, V0 @18432, V1 @23040

    const int tid = threadIdx.x;
    const int lane = tid & 31, wid = tid >> 5;
    const int q4 = lane >> 2, qt2 = (lane & 3) * 2;
    const int qtile = gridDim.x - 1 - blockIdx.x;    // big tiles first
    const int bh = blockIdx.y, b = bh >> 4, h = bh & 15;
    const int r0 = qtile * 128;

    const int ar = (lane & 7) + ((lane >> 3) & 1) * 8;
    const int ak = (lane >> 4) * 8;
    const int br = (lane & 7) + ((lane >> 4) & 1) * 8;
    const int bk = ((lane >> 3) & 1) * 8;

    // load Q (128 rows x 64 halves)
    {
        const __half* Qg = QKVh + ((size_t)(b * Sn + r0)) * 3072 + h * 64;
        #pragma unroll
        for (int i = 0; i < 4; i++) {
            int id = tid + i * 256;          // 0..1023
            int row = id >> 3, c = (id & 7) * 8;
            cpasync16(sB + (row * FSTR + c) * 2, Qg + (size_t)row * 3072 + c);
        }
        cp_commit();
    }

    auto loadKV = [&](int kt, int buf) {
        const __half* Kg = QKVh + ((size_t)(b * Sn + kt * 64)) * 3072 + 1024 + h * 64;
        const __half* Vg = Vth + ((size_t)bh * 64) * Sn + kt * 64;
        const uint32_t kB = sB + (FA_Q_H + buf * FA_KV_H) * 2;
        const uint32_t vB = sB + (FA_Q_H + (2 + buf) * FA_KV_H) * 2;
        #pragma unroll
        for (int i = 0; i < 2; i++) {
            int id = tid + i * 256;          // 0..511
            int row = id >> 3, c = (id & 7) * 8;
            cpasync16(kB + (row * FSTR + c) * 2, Kg + (size_t)row * 3072 + c);
            cpasync16(vB + (row * FSTR + c) * 2, Vg + (size_t)row * Sn + c);
        }
        cp_commit();
    };

    loadKV(0, 0);

    asm volatile("cp.async.wait_group 1;" ::: "memory");   // Q ready
    __syncthreads();
    uint32_t aQ[4][4];
    #pragma unroll
    for (int kcc = 0; kcc < 4; kcc++)
        ldsm_x4(aQ[kcc], sB + ((wid * 16 + ar) * FSTR + kcc * 16 + ak) * 2);

    const int rowg0 = r0 + wid * 16 + q4;
    const int rowg1 = rowg0 + 8;
    const int wrow_max = r0 + wid * 16 + 15;

    float m0 = NEG_INF, m1 = NEG_INF, l0 = 0.f, l1 = 0.f;
    float o[8][4] = {};

    const int ntk = 2 * qtile + 2;
    for (int kt = 0; kt < ntk; kt++) {
        const int buf = kt & 1;
        if (kt + 1 < ntk) {
            loadKV(kt + 1, buf ^ 1);
            asm volatile("cp.async.wait_group 1;" ::: "memory");
        } else {
            asm volatile("cp.async.wait_group 0;" ::: "memory");
        }
        __syncthreads();

        const int gk0 = kt * 64;
        if (gk0 <= wrow_max) {
            const uint32_t kB = sB + (FA_Q_H + buf * FA_KV_H) * 2;
            const uint32_t vB = sB + (FA_Q_H + (2 + buf) * FA_KV_H) * 2;

            float s[8][4] = {};
            #pragma unroll
            for (int kcc = 0; kcc < 4; kcc++) {
                uint32_t bf4[4][4];
                #pragma unroll
                for (int np = 0; np < 4; np++)
                    ldsm_x4(bf4[np], kB + ((np * 16 + br) * FSTR + kcc * 16 + bk) * 2);
                #pragma unroll
                for (int nt = 0; nt < 8; nt++)
                    mma_f16(s[nt], aQ[kcc], &bf4[nt >> 1][(nt & 1) * 2]);
            }

            const int colb = gk0 + qt2;
            float mx0 = NEG_INF, mx1 = NEG_INF;
            #pragma unroll
            for (int nt = 0; nt < 8; nt++) {
                const int c0 = colb + nt * 8;
                s[nt][0] = (c0     <= rowg0) ? s[nt][0] * 0.125f : NEG_INF;
                s[nt][1] = (c0 + 1 <= rowg0) ? s[nt][1] * 0.125f : NEG_INF;
                s[nt][2] = (c0     <= rowg1) ? s[nt][2] * 0.125f : NEG_INF;
                s[nt][3] = (c0 + 1 <= rowg1) ? s[nt][3] * 0.125f : NEG_INF;
                mx0 = fmaxf(mx0, fmaxf(s[nt][0], s[nt][1]));
                mx1 = fmaxf(mx1, fmaxf(s[nt][2], s[nt][3]));
            }
            mx0 = fmaxf(mx0, __shfl_xor_sync(0xffffffffu, mx0, 1));
            mx0 = fmaxf(mx0, __shfl_xor_sync(0xffffffffu, mx0, 2));
            mx1 = fmaxf(mx1, __shfl_xor_sync(0xffffffffu, mx1, 1));
            mx1 = fmaxf(mx1, __shfl_xor_sync(0xffffffffu, mx1, 2));

            const float mn0 = fmaxf(m0, mx0), mn1 = fmaxf(m1, mx1);
            const float sc0 = __expf(m0 - mn0), sc1 = __expf(m1 - mn1);
            m0 = mn0; m1 = mn1;

            float rs0 = 0.f, rs1 = 0.f;
            uint32_t pf[4][4];
            #pragma unroll
            for (int nt = 0; nt < 8; nt++) {
                float p0 = __expf(s[nt][0] - m0);
                float p1 = __expf(s[nt][1] - m0);
                float p2 = __expf(s[nt][2] - m1);
                float p3 = __expf(s[nt][3] - m1);
                rs0 += p0 + p1; rs1 += p2 + p3;
                __half2 h01 = __floats2half2_rn(p0, p1);
                __half2 h23 = __floats2half2_rn(p2, p3);
                pf[nt >> 1][(nt & 1) * 2 + 0] = *(uint32_t*)&h01;
                pf[nt >> 1][(nt & 1) * 2 + 1] = *(uint32_t*)&h23;
            }
            rs0 += __shfl_xor_sync(0xffffffffu, rs0, 1);
            rs0 += __shfl_xor_sync(0xffffffffu, rs0, 2);
            rs1 += __shfl_xor_sync(0xffffffffu, rs1, 1);
            rs1 += __shfl_xor_sync(0xffffffffu, rs1, 2);
            l0 = l0 * sc0 + rs0;
            l1 = l1 * sc1 + rs1;

            #pragma unroll
            for (int nt = 0; nt < 8; nt++) {
                o[nt][0] *= sc0; o[nt][1] *= sc0;
                o[nt][2] *= sc1; o[nt][3] *= sc1;
            }

            #pragma unroll
            for (int kcc = 0; kcc < 4; kcc++) {
                uint32_t bf4[4][4];
                #pragma unroll
                for (int np = 0; np < 4; np++)
                    ldsm_x4(bf4[np], vB + ((np * 16 + br) * FSTR + kcc * 16 + bk) * 2);
                #pragma unroll
                for (int nt = 0; nt < 8; nt++)
                    mma_f16(o[nt], pf[kcc], &bf4[nt >> 1][(nt & 1) * 2]);
            }
        }
        __syncthreads();
    }

    const float li0 = 1.0f / l0, li1 = 1.0f / l1;
    __half* Op0 = O + ((size_t)(b * Sn + rowg0)) * Dn + h * 64 + qt2;
    __half* Op1 = O + ((size_t)(b * Sn + rowg1)) * Dn + h * 64 + qt2;
    #pragma unroll
    for (int nt = 0; nt < 8; nt++) {
        __half2 h0 = __floats2half2_rn(o[nt][0] * li0, o[nt][1] * li0);
        __half2 h1 = __floats2half2_rn(o[nt][2] * li1, o[nt][3] * li1);
        *(__half2*)(Op0 + nt * 8) = h0;
        *(__half2*)(Op1 + nt * 8) = h1;
    }
}

// ---------------- LayerNorm: one block per row of 1024 -----------------------
__global__ void __launch_bounds__(256)
ln_kernel(const float* __restrict__ X, const float* __restrict__ G,
          const float* __restrict__ Bt, float* __restrict__ Y,
          __half* __restrict__ Yh) {
    const int row = blockIdx.x;
    const int t = threadIdx.x;
    const float* x = X + (size_t)row * Dn;

    float4 v = *(const float4*)(x + t * 4);
    float s  = v.x + v.y + v.z + v.w;
    float sq = v.x * v.x + v.y * v.y + v.z * v.z + v.w * v.w;
    #pragma unroll
    for (int off = 16; off; off >>= 1) {
        s  += __shfl_xor_sync(0xffffffffu, s,  off);
        sq += __shfl_xor_sync(0xffffffffu, sq, off);
    }
    __shared__ float rs[8], rq[8];
    int wid = t >> 5, lane = t & 31;
    if (lane == 0) { rs[wid] = s; rq[wid] = sq; }
    __syncthreads();
    if (t == 0) {
        float S = 0.f, Q = 0.f;
        #pragma unroll
        for (int i = 0; i < 8; i++) { S += rs[i]; Q += rq[i]; }
        float mean = S * (1.0f / Dn);
        float var  = Q * (1.0f / Dn) - mean * mean;
        rs[0] = mean;
        rq[0] = rsqrtf(var + 1e-5f);
    }
    __syncthreads();
    const float mean = rs[0], rstd = rq[0];

    float4 gv = *(const float4*)(G + t * 4);
    float4 bv = *(const float4*)(Bt + t * 4);
    float4 y;
    y.x = (v.x - mean) * rstd * gv.x + bv.x;
    y.y = (v.y - mean) * rstd * gv.y + bv.y;
    y.z = (v.z - mean) * rstd * gv.z + bv.z;
    y.w = (v.w - mean) * rstd * gv.w + bv.w;
    *(float4*)(Y + (size_t)row * Dn + t * 4) = y;
    if (Yh) {
        __half2 h0 = __floats2half2_rn(y.x, y.y);
        __half2 h1 = __floats2half2_rn(y.z, y.w);
        *(uint2*)(Yh + (size_t)row * Dn + t * 4) =
            make_uint2(*(uint32_t*)&h0, *(uint32_t*)&h1);
    }
}

// ---------------- launch ----------------
extern "C" void kernel_launch(void* const* d_in, const int* in_sizes, int n_in,
                              void* d_out, int out_size) {
    const float* x   = (const float*)d_in[0];
    const float* wq  = (const float*)d_in[1];
    const float* bq  = (const float*)d_in[2];
    const float* wk  = (const float*)d_in[3];
    const float* bk  = (const float*)d_in[4];
    const float* wv  = (const float*)d_in[5];
    const float* bv  = (const float*)d_in[6];
    const float* wo  = (const float*)d_in[7];
    const float* bo  = (const float*)d_in[8];
    const float* w1  = (const float*)d_in[9];
    const float* b1  = (const float*)d_in[10];
    const float* w2  = (const float*)d_in[11];
    const float* b2  = (const float*)d_in[12];
    const float* g1  = (const float*)d_in[13];
    const float* be1 = (const float*)d_in[14];
    const float* g2  = (const float*)d_in[15];
    const float* be2 = (const float*)d_in[16];

    __half *WqkvT, *WoT, *W1T, *W2T, *xh, *QKVh, *Vth, *Oh, *Hhh, *FFh;
    float *Bqkv, *T, *Hh;
    cudaGetSymbolAddress((void**)&WqkvT, g_WqkvT);
    cudaGetSymbolAddress((void**)&Bqkv,  g_Bqkv);
    cudaGetSymbolAddress((void**)&WoT,   g_WoT);
    cudaGetSymbolAddress((void**)&W1T,   g_W1T);
    cudaGetSymbolAddress((void**)&W2T,   g_W2T);
    cudaGetSymbolAddress((void**)&xh,    g_xh);
    cudaGetSymbolAddress((void**)&QKVh,  g_QKVh);
    cudaGetSymbolAddress((void**)&Vth,   g_Vth);
    cudaGetSymbolAddress((void**)&Oh,    g_Oh);
    cudaGetSymbolAddress((void**)&T,     g_T);
    cudaGetSymbolAddress((void**)&Hh,    g_Hh);
    cudaGetSymbolAddress((void**)&Hhh,   g_Hhh);
    cudaGetSymbolAddress((void**)&FFh,   g_FFh);

    cudaFuncSetAttribute(hgemm<EPI_BIASH>, cudaFuncAttributeMaxDynamicSharedMemorySize, GEMM_SMEM);
    cudaFuncSetAttribute(hgemm<EPI_GELUH>, cudaFuncAttributeMaxDynamicSharedMemorySize, GEMM_SMEM);
    cudaFuncSetAttribute(hgemm<EPI_RES>,   cudaFuncAttributeMaxDynamicSharedMemorySize, GEMM_SMEM);
    cudaFuncSetAttribute(fattn, cudaFuncAttributeMaxDynamicSharedMemorySize, FA_SMEM);

    // 0) weight repacks + x -> fp16
    repack_qkvT<<<(3 * Dn * Dn + 255) / 256, 256>>>(wq, wk, wv, bq, bk, bv);
    transpose_kh<<<dim3(Dn / 32, Dn / 32),  dim3(32, 8)>>>(WoT, wo, Dn, Dn);
    transpose_kh<<<dim3(FFn / 32, Dn / 32), dim3(32, 8)>>>(W1T, w1, Dn, FFn);
    transpose_kh<<<dim3(Dn / 32, FFn / 32), dim3(32, 8)>>>(W2T, w2, FFn, Dn);
    f2h<<<(Mn * Dn / 4 + 255) / 256, 256>>>(x, xh, Mn * Dn / 4);

    // 1) QKV projection -> fp16
    hgemm<EPI_BIASH><<<dim3(3 * Dn / 128, Mn / 128), 128, GEMM_SMEM>>>(
        xh, WqkvT, Bqkv, nullptr, nullptr, QKVh, Mn, 3 * Dn, Dn);
    // 1b) V transpose per head
    vtrans<<<dim3(Sn / 32, HDn / 32, 64), dim3(32, 8)>>>(QKVh, Vth);
    // 2) tensor-core causal flash attention -> Oh (fp16)
    fattn<<<dim3(Sn / 128, 64), 256, FA_SMEM>>>(QKVh, Vth, Oh);
    // 3) O projection + residual x
    hgemm<EPI_RES><<<dim3(Dn / 128, Mn / 128), 128, GEMM_SMEM>>>(
        Oh, WoT, bo, x, T, nullptr, Mn, Dn, Dn);
    // 4) LayerNorm 1 (fp32 + fp16 twin)
    ln_kernel<<<Mn, 256>>>(T, g1, be1, Hh, Hhh);
    // 5) FFN up + exact GELU -> fp16
    hgemm<EPI_GELUH><<<dim3(FFn / 128, Mn / 128), 128, GEMM_SMEM>>>(
        Hhh, W1T, b1, nullptr, nullptr, FFh, Mn, FFn, Dn);
    // 6) FFN down + residual Hh
    hgemm<EPI_RES><<<dim3(Dn / 128, Mn / 128), 128, GEMM_SMEM>>>(
        FFh, W2T, b2, Hh, T, nullptr, Mn, Dn, FFn);
    // 7) LayerNorm 2 -> output
    ln_kernel<<<Mn, 256>>>(T, g2, be2, (float*)d_out, nullptr);
}

// round 12
// speedup vs baseline: 1.0812x; 1.0216x over previous
#include <cuda_runtime.h>
#include <cuda_fp16.h>
#include <math.h>
#include <stdint.h>

// Problem constants
constexpr int Bn  = 4;
constexpr int Sn  = 2048;
constexpr int Dn  = 1024;
constexpr int HDn = 64;
constexpr int FFn = 4096;
constexpr int Mn  = Bn * Sn;        // 8192 rows
constexpr float NEG_INF = -1.0e30f;

// ---------------- scratch (static __device__, no allocations) ----------------
__device__ __half g_WqkvT[3 * Dn * Dn];        // [N=3072][K=1024] K-major, fp16
__device__ float  g_Bqkv [3 * Dn];
__device__ __half g_WoT  [Dn * Dn];
__device__ __half g_W1T  [FFn * Dn];
__device__ __half g_W2T  [Dn * FFn];
__device__ __half g_xh  [(size_t)Mn * Dn];     // fp16 copy of x
__device__ __half g_QKVh[(size_t)Mn * 3 * Dn]; // q|k|v per row (fp16)
__device__ __half g_Oh  [(size_t)Mn * Dn];     // attention out (fp16)
__device__ float  g_T   [(size_t)Mn * Dn];     // residual temp
__device__ float  g_Hh  [(size_t)Mn * Dn];     // post-LN1 hidden (fp32)
__device__ __half g_Hhh [(size_t)Mn * Dn];     // post-LN1 hidden (fp16)
__device__ __half g_FFh [(size_t)Mn * FFn];    // FFN intermediate (fp16)

// ---------------- helpers ----------------
__device__ __forceinline__ uint32_t smem_u32(const void* p) {
    return (uint32_t)__cvta_generic_to_shared(p);
}
__device__ __forceinline__ void cpasync16(uint32_t dst, const void* src) {
    asm volatile("cp.async.ca.shared.global [%0], [%1], 16;" :: "r"(dst), "l"(src) : "memory");
}
__device__ __forceinline__ void cp_commit() {
    asm volatile("cp.async.commit_group;" ::: "memory");
}
__device__ __forceinline__ void mma_f16(float* c, const uint32_t* a, const uint32_t* b) {
    asm volatile(
        "mma.sync.aligned.m16n8k16.row.col.f32.f16.f16.f32 "
        "{%0,%1,%2,%3}, {%4,%5,%6,%7}, {%8,%9}, {%0,%1,%2,%3};"
        : "+f"(c[0]), "+f"(c[1]), "+f"(c[2]), "+f"(c[3])
        : "r"(a[0]), "r"(a[1]), "r"(a[2]), "r"(a[3]), "r"(b[0]), "r"(b[1]));
}
__device__ __forceinline__ void ldsm_x4(uint32_t* r, uint32_t addr) {
    asm volatile("ldmatrix.sync.aligned.m8n8.x4.shared.b16 {%0,%1,%2,%3}, [%4];"
                 : "=r"(r[0]), "=r"(r[1]), "=r"(r[2]), "=r"(r[3]) : "r"(addr));
}
__device__ __forceinline__ void ldsm_x4_t(uint32_t* r, uint32_t addr) {
    asm volatile("ldmatrix.sync.aligned.m8n8.x4.trans.shared.b16 {%0,%1,%2,%3}, [%4];"
                 : "=r"(r[0]), "=r"(r[1]), "=r"(r[2]), "=r"(r[3]) : "r"(addr));
}

// ---------------- unified prologue kernel ------------------------------------
// One launch does: qkv weight repack (+bias pack), wo/w1/w2 transposes (fp32 ->
// fp16 K-major), and x -> fp16. Jobs are dispatched by linear block id so all
// run concurrently and fill the device.
constexpr int PB_QKV = (3 * Dn * Dn) / 256;                    // 12288
constexpr int PB_WO  = (Dn / 32) * (Dn / 32);                  // 1024
constexpr int PB_W1  = (FFn / 32) * (Dn / 32);                 // 4096
constexpr int PB_W2  = (Dn / 32) * (FFn / 32);                 // 4096
constexpr int PB_F2H = (Mn * Dn / 4) / 256;                    // 8192
constexpr int PB_TOTAL = PB_QKV + PB_WO + PB_W1 + PB_W2 + PB_F2H;

__device__ __forceinline__ void prep_transpose(
    __half* __restrict__ dst, const float* __restrict__ src,
    int R, int C, int local, int tid) {
    __shared__ float tile[32][33];
    int bx = local % (C / 32), by = local / (C / 32);
    int c0 = bx * 32, r0 = by * 32;
    int tx = tid & 31, ty = tid >> 5;          // 32 x 8
    #pragma unroll
    for (int i = 0; i < 32; i += 8)
        tile[ty + i][tx] = src[(size_t)(r0 + ty + i) * C + c0 + tx];
    __syncthreads();
    #pragma unroll
    for (int i = 0; i < 32; i += 8)
        dst[(size_t)(c0 + ty + i) * R + r0 + tx] = __float2half(tile[tx][ty + i]);
}

__global__ void __launch_bounds__(256)
prep(const float* __restrict__ x,
     const float* __restrict__ wq, const float* __restrict__ wk,
     const float* __restrict__ wv, const float* __restrict__ bq,
     const float* __restrict__ bk, const float* __restrict__ bv,
     const float* __restrict__ wo, const float* __restrict__ w1,
     const float* __restrict__ w2) {
    const int bid = blockIdx.x;
    const int tid = threadIdx.x;

    if (bid < PB_QKV) {
        int gid = bid * 256 + tid;
        {
            int n = gid >> 10;              // output row (N index)
            int d = gid & 1023;             // K index
            int which = n >> 10;
            int c = n & 1023;
            int h = c >> 6, f = c & 63;
            const float* w = (which == 0) ? wq : (which == 1) ? wk : wv;
            g_WqkvT[gid] = __float2half(w[((size_t)h * Dn + d) * HDn + f]);
        }
        if (gid < 3 * Dn) {
            int which = gid >> 10; int c = gid & 1023;
            const float* b = (which == 0) ? bq : (which == 1) ? bk : bv;
            g_Bqkv[gid] = b[c];
        }
    } else if (bid < PB_QKV + PB_WO) {
        prep_transpose(g_WoT, wo, Dn, Dn, bid - PB_QKV, tid);
    } else if (bid < PB_QKV + PB_WO + PB_W1) {
        prep_transpose(g_W1T, w1, Dn, FFn, bid - PB_QKV - PB_WO, tid);
    } else if (bid < PB_QKV + PB_WO + PB_W1 + PB_W2) {
        prep_transpose(g_W2T, w2, FFn, Dn, bid - PB_QKV - PB_WO - PB_W1, tid);
    } else {
        int i = (bid - (PB_QKV + PB_WO + PB_W1 + PB_W2)) * 256 + tid;
        float4 v = *(const float4*)(x + (size_t)i * 4);
        __half2 h0 = __floats2half2_rn(v.x, v.y);
        __half2 h1 = __floats2half2_rn(v.z, v.w);
        *(uint2*)(g_xh + (size_t)i * 4) = make_uint2(*(uint32_t*)&h0, *(uint32_t*)&h1);
    }
}

// ---------------- fp16 tensor GEMM 128x128x32, 3-stage cp.async --------------
// 128 threads = 4 warps (2m x 2n); warp tile 64x64; 2 CTAs/SM.
// 3 stages -> ONE __syncthreads per k-iter. SMEM rows of 40 halves.
enum { EPI_BIAS = 0, EPI_GELUH = 1, EPI_RES = 2, EPI_BIASH = 3 };

__device__ __forceinline__ float gelu_f(float x) {
    return 0.5f * x * (1.0f + erff(x * 0.70710678118654752440f));
}

constexpr int ASTRH = 40;                     // smem row stride in halves
constexpr int G3_A_H  = 128 * ASTRH;          // 5120 halves per matrix
constexpr int G3_STG_H = 2 * G3_A_H;          // 10240 halves per stage (A+B)
constexpr int GEMM_SMEM = 3 * G3_STG_H * 2;   // 61440 B

template <int EPI>
__global__ void __launch_bounds__(128, 2)
hgemm(const __half* __restrict__ A, const __half* __restrict__ Bt,
      const float* __restrict__ bias, const float* __restrict__ Res,
      float* __restrict__ C, __half* __restrict__ Ch, int M, int N, int K) {
    extern __shared__ __half sh[];
    const uint32_t sB = smem_u32(sh);

    const int tid  = threadIdx.x;
    const int lane = tid & 31, wid = tid >> 5;
    const int quad = lane >> 2, qt = lane & 3;
    const int wm = wid & 1, wn = wid >> 1;
    const int m0 = blockIdx.y * 128, n0 = blockIdx.x * 128;

    const int rL = tid >> 2;
    const int kc = (tid & 3) * 8;

    // LDSM per-thread address offsets (bytes) within a stage buffer.
    uint32_t aOff[4], bOff[4];
    {
        const int ar = (lane & 7) + ((lane >> 3) & 1) * 8;
        const int ak = (lane >> 4) * 8;
        #pragma unroll
        for (int mt = 0; mt < 4; mt++)
            aOff[mt] = ((wm * 64 + mt * 16 + ar) * ASTRH + ak) * 2;
        const int br = (lane & 7) + ((lane >> 4) & 1) * 8;
        const int bk = ((lane >> 3) & 1) * 8;
        #pragma unroll
        for (int np = 0; np < 4; np++)
            bOff[np] = ((wn * 64 + np * 16 + br) * ASTRH + bk) * 2;
    }

    float acc[4][8][4] = {};

    auto load_tile = [&](int kt, int s) {
        const uint32_t aB = sB + s * (G3_STG_H * 2);
        const uint32_t bB = aB + G3_A_H * 2;
        const __half* Ap = A  + (size_t)m0 * K + (size_t)kt * 32 + kc;
        const __half* Bp = Bt + (size_t)n0 * K + (size_t)kt * 32 + kc;
        #pragma unroll
        for (int i = 0; i < 4; i++) {
            int row = rL + i * 32;
            uint32_t off = row * (ASTRH * 2) + kc * 2;
            cpasync16(aB + off, Ap + (size_t)row * K);
            cpasync16(bB + off, Bp + (size_t)row * K);
        }
        cp_commit();
    };

    const int NT = K >> 5;
    load_tile(0, 0);
    load_tile(1, 1);

    for (int kt = 0; kt < NT; kt++) {
        asm volatile("cp.async.wait_group 1;" ::: "memory");  // stage kt ready
        __syncthreads();                                      // iter kt-1 reads done
        if (kt + 2 < NT) load_tile(kt + 2, (kt + 2) % 3);
        else             cp_commit();                         // keep group order

        const uint32_t AbU = sB + (kt % 3) * (G3_STG_H * 2);
        const uint32_t BbU = AbU + G3_A_H * 2;
        #pragma unroll
        for (int ks = 0; ks < 2; ks++) {
            const uint32_t kbB = ks * 16 * 2;
            uint32_t af[4][4], bf4[4][4];
            #pragma unroll
            for (int mt = 0; mt < 4; mt++)
                ldsm_x4(af[mt], AbU + aOff[mt] + kbB);
            #pragma unroll
            for (int np = 0; np < 4; np++)
                ldsm_x4(bf4[np], BbU + bOff[np] + kbB);
            #pragma unroll
            for (int mt = 0; mt < 4; mt++)
                #pragma unroll
                for (int nt = 0; nt < 8; nt++)
                    mma_f16(acc[mt][nt], af[mt], &bf4[nt >> 1][(nt & 1) * 2]);
        }
    }

    #pragma unroll
    for (int mt = 0; mt < 4; mt++) {
        const int r0 = m0 + wm * 64 + mt * 16 + quad;
        #pragma unroll
        for (int nt = 0; nt < 8; nt++) {
            const int col = n0 + wn * 64 + nt * 8 + qt * 2;
            const float2 bv2 = *(const float2*)&bias[col];
            #pragma unroll
            for (int half = 0; half < 2; half++) {
                const int r = r0 + half * 8;
                float2 y;
                y.x = acc[mt][nt][half * 2 + 0] + bv2.x;
                y.y = acc[mt][nt][half * 2 + 1] + bv2.y;
                size_t base = (size_t)r * N + col;
                if (EPI == EPI_GELUH) {
                    y.x = gelu_f(y.x); y.y = gelu_f(y.y);
                    __half2 hh = __floats2half2_rn(y.x, y.y);
                    *(__half2*)&Ch[base] = hh;
                } else if (EPI == EPI_BIASH) {
                    __half2 hh = __floats2half2_rn(y.x, y.y);
                    *(__half2*)&Ch[base] = hh;
                } else if (EPI == EPI_RES) {
                    float2 rr = *(const float2*)&Res[base];
                    y.x += rr.x; y.y += rr.y;
                    *(float2*)&C[base] = y;
                } else {
                    *(float2*)&C[base] = y;
                }
            }
        }
    }
}

// ---------------- tensor-core causal flash attention v3 ----------------------
// 256 threads = 8 warps; CTA = 128 query rows x one (b,h); warp = 16 rows.
// K AND V both loaded from QKVh natural [key][hd] layout; V's PV B-fragments
// come from ldmatrix.trans (no pre-transposed V buffer needed).
constexpr int FSTR = 72;
constexpr int FA_Q_H  = 128 * FSTR;               // 9216
constexpr int FA_KV_H = 64 * FSTR;                // 4608
constexpr int FA_SMEM = (FA_Q_H + 4 * FA_KV_H) * 2;   // 55296 B

__global__ void __launch_bounds__(256, 2)
fattn(const __half* __restrict__ QKVh, __half* __restrict__ O) {
    extern __shared__ __half fs[];
    const uint32_t sB = smem_u32(fs);
    // halves layout: Q @0, K0 @9216, K1 @13824, V0 @18432, V1 @23040

    const int tid = threadIdx.x;
    const int lane = tid & 31, wid = tid >> 5;
    const int q4 = lane >> 2, qt2 = (lane & 3) * 2;
    const int qtile = gridDim.x - 1 - blockIdx.x;    // big tiles first
    const int bh = blockIdx.y, b = bh >> 4, h = bh & 15;
    const int r0 = qtile * 128;

    const int ar = (lane & 7) + ((lane >> 3) & 1) * 8;
    const int ak = (lane >> 4) * 8;
    const int br = (lane & 7) + ((lane >> 4) & 1) * 8;
    const int bk = ((lane >> 3) & 1) * 8;

    // load Q (128 rows x 64 halves)
    {
        const __half* Qg = QKVh + ((size_t)(b * Sn + r0)) * 3072 + h * 64;
        #pragma unroll
        for (int i = 0; i < 4; i++) {
            int id = tid + i * 256;          // 0..1023
            int row = id >> 3, c = (id & 7) * 8;
            cpasync16(sB + (row * FSTR + c) * 2, Qg + (size_t)row * 3072 + c);
        }
        cp_commit();
    }

    auto loadKV = [&](int kt, int buf) {
        const __half* Kg = QKVh + ((size_t)(b * Sn + kt * 64)) * 3072 + 1024 + h * 64;
        const __half* Vg = Kg + 1024;        // V rows right after K in same row
        const uint32_t kB = sB + (FA_Q_H + buf * FA_KV_H) * 2;
        const uint32_t vB = sB + (FA_Q_H + (2 + buf) * FA_KV_H) * 2;
        #pragma unroll
        for (int i = 0; i < 2; i++) {
            int id = tid + i * 256;          // 0..511
            int row = id >> 3, c = (id & 7) * 8;
            cpasync16(kB + (row * FSTR + c) * 2, Kg + (size_t)row * 3072 + c);
            cpasync16(vB + (row * FSTR + c) * 2, Vg + (size_t)row * 3072 + c);
        }
        cp_commit();
    };

    loadKV(0, 0);

    asm volatile("cp.async.wait_group 1;" ::: "memory");   // Q ready
    __syncthreads();
    uint32_t aQ[4][4];
    #pragma unroll
    for (int kcc = 0; kcc < 4; kcc++)
        ldsm_x4(aQ[kcc], sB + ((wid * 16 + ar) * FSTR + kcc * 16 + ak) * 2);

    const int rowg0 = r0 + wid * 16 + q4;
    const int rowg1 = rowg0 + 8;
    const int wrow_max = r0 + wid * 16 + 15;

    float m0 = NEG_INF, m1 = NEG_INF, l0 = 0.f, l1 = 0.f;
    float o[8][4] = {};

    const int ntk = 2 * qtile + 2;
    for (int kt = 0; kt < ntk; kt++) {
        const int buf = kt & 1;
        if (kt + 1 < ntk) {
            loadKV(kt + 1, buf ^ 1);
            asm volatile("cp.async.wait_group 1;" ::: "memory");
        } else {
            asm volatile("cp.async.wait_group 0;" ::: "memory");
        }
        __syncthreads();

        const int gk0 = kt * 64;
        if (gk0 <= wrow_max) {
            const uint32_t kB = sB + (FA_Q_H + buf * FA_KV_H) * 2;
            const uint32_t vB = sB + (FA_Q_H + (2 + buf) * FA_KV_H) * 2;

            float s[8][4] = {};
            #pragma unroll
            for (int kcc = 0; kcc < 4; kcc++) {
                uint32_t bf4[4][4];
                #pragma unroll
                for (int np = 0; np < 4; np++)
                    ldsm_x4(bf4[np], kB + ((np * 16 + br) * FSTR + kcc * 16 + bk) * 2);
                #pragma unroll
                for (int nt = 0; nt < 8; nt++)
                    mma_f16(s[nt], aQ[kcc], &bf4[nt >> 1][(nt & 1) * 2]);
            }

            const int colb = gk0 + qt2;
            float mx0 = NEG_INF, mx1 = NEG_INF;
            #pragma unroll
            for (int nt = 0; nt < 8; nt++) {
                const int c0 = colb + nt * 8;
                s[nt][0] = (c0     <= rowg0) ? s[nt][0] * 0.125f : NEG_INF;
                s[nt][1] = (c0 + 1 <= rowg0) ? s[nt][1] * 0.125f : NEG_INF;
                s[nt][2] = (c0     <= rowg1) ? s[nt][2] * 0.125f : NEG_INF;
                s[nt][3] = (c0 + 1 <= rowg1) ? s[nt][3] * 0.125f : NEG_INF;
                mx0 = fmaxf(mx0, fmaxf(s[nt][0], s[nt][1]));
                mx1 = fmaxf(mx1, fmaxf(s[nt][2], s[nt][3]));
            }
            mx0 = fmaxf(mx0, __shfl_xor_sync(0xffffffffu, mx0, 1));
            mx0 = fmaxf(mx0, __shfl_xor_sync(0xffffffffu, mx0, 2));
            mx1 = fmaxf(mx1, __shfl_xor_sync(0xffffffffu, mx1, 1));
            mx1 = fmaxf(mx1, __shfl_xor_sync(0xffffffffu, mx1, 2));

            const float mn0 = fmaxf(m0, mx0), mn1 = fmaxf(m1, mx1);
            const float sc0 = __expf(m0 - mn0), sc1 = __expf(m1 - mn1);
            m0 = mn0; m1 = mn1;

            float rs0 = 0.f, rs1 = 0.f;
            uint32_t pf[4][4];
            #pragma unroll
            for (int nt = 0; nt < 8; nt++) {
                float p0 = __expf(s[nt][0] - m0);
                float p1 = __expf(s[nt][1] - m0);
                float p2 = __expf(s[nt][2] - m1);
                float p3 = __expf(s[nt][3] - m1);
                rs0 += p0 + p1; rs1 += p2 + p3;
                __half2 h01 = __floats2half2_rn(p0, p1);
                __half2 h23 = __floats2half2_rn(p2, p3);
                pf[nt >> 1][(nt & 1) * 2 + 0] = *(uint32_t*)&h01;
                pf[nt >> 1][(nt & 1) * 2 + 1] = *(uint32_t*)&h23;
            }
            rs0 += __shfl_xor_sync(0xffffffffu, rs0, 1);
            rs0 += __shfl_xor_sync(0xffffffffu, rs0, 2);
            rs1 += __shfl_xor_sync(0xffffffffu, rs1, 1);
            rs1 += __shfl_xor_sync(0xffffffffu, rs1, 2);
            l0 = l0 * sc0 + rs0;
            l1 = l1 * sc1 + rs1;

            #pragma unroll
            for (int nt = 0; nt < 8; nt++) {
                o[nt][0] *= sc0; o[nt][1] *= sc0;
                o[nt][2] *= sc1; o[nt][3] *= sc1;
            }

            // PV: V stored [key][hd]; ldsm.trans yields col-B fragments of V^T.
            // matrix g (lanes 8g..8g+7): k rows = (g&1)*8 + ar-lanes, n += (g>>1)*8
            #pragma unroll
            for (int kcc = 0; kcc < 4; kcc++) {
                uint32_t bf4[4][4];
                #pragma unroll
                for (int np = 0; np < 4; np++)
                    ldsm_x4_t(bf4[np], vB + ((kcc * 16 + ar) * FSTR + np * 16 + ak) * 2);
                #pragma unroll
                for (int nt = 0; nt < 8; nt++)
                    mma_f16(o[nt], pf[kcc], &bf4[nt >> 1][(nt & 1) * 2]);
            }
        }
        __syncthreads();
    }

    const float li0 = 1.0f / l0, li1 = 1.0f / l1;
    __half* Op0 = O + ((size_t)(b * Sn + rowg0)) * Dn + h * 64 + qt2;
    __half* Op1 = O + ((size_t)(b * Sn + rowg1)) * Dn + h * 64 + qt2;
    #pragma unroll
    for (int nt = 0; nt < 8; nt++) {
        __half2 h0 = __floats2half2_rn(o[nt][0] * li0, o[nt][1] * li0);
        __half2 h1 = __floats2half2_rn(o[nt][2] * li1, o[nt][3] * li1);
        *(__half2*)(Op0 + nt * 8) = h0;
        *(__half2*)(Op1 + nt * 8) = h1;
    }
}

// ---------------- LayerNorm: one block per row of 1024 -----------------------
__global__ void __launch_bounds__(256)
ln_kernel(const float* __restrict__ X, const float* __restrict__ G,
          const float* __restrict__ Bt, float* __restrict__ Y,
          __half* __restrict__ Yh) {
    const int row = blockIdx.x;
    const int t = threadIdx.x;
    const float* x = X + (size_t)row * Dn;

    float4 v = *(const float4*)(x + t * 4);
    float s  = v.x + v.y + v.z + v.w;
    float sq = v.x * v.x + v.y * v.y + v.z * v.z + v.w * v.w;
    #pragma unroll
    for (int off = 16; off; off >>= 1) {
        s  += __shfl_xor_sync(0xffffffffu, s,  off);
        sq += __shfl_xor_sync(0xffffffffu, sq, off);
    }
    __shared__ float rs[8], rq[8];
    int wid = t >> 5, lane = t & 31;
    if (lane == 0) { rs[wid] = s; rq[wid] = sq; }
    __syncthreads();
    if (t == 0) {
        float S = 0.f, Q = 0.f;
        #pragma unroll
        for (int i = 0; i < 8; i++) { S += rs[i]; Q += rq[i]; }
        float mean = S * (1.0f / Dn);
        float var  = Q * (1.0f / Dn) - mean * mean;
        rs[0] = mean;
        rq[0] = rsqrtf(var + 1e-5f);
    }
    __syncthreads();
    const float mean = rs[0], rstd = rq[0];

    float4 gv = *(const float4*)(G + t * 4);
    float4 bv = *(const float4*)(Bt + t * 4);
    float4 y;
    y.x = (v.x - mean) * rstd * gv.x + bv.x;
    y.y = (v.y - mean) * rstd * gv.y + bv.y;
    y.z = (v.z - mean) * rstd * gv.z + bv.z;
    y.w = (v.w - mean) * rstd * gv.w + bv.w;
    *(float4*)(Y + (size_t)row * Dn + t * 4) = y;
    if (Yh) {
        __half2 h0 = __floats2half2_rn(y.x, y.y);
        __half2 h1 = __floats2half2_rn(y.z, y.w);
        *(uint2*)(Yh + (size_t)row * Dn + t * 4) =
            make_uint2(*(uint32_t*)&h0, *(uint32_t*)&h1);
    }
}

// ---------------- launch ----------------
extern "C" void kernel_launch(void* const* d_in, const int* in_sizes, int n_in,
                              void* d_out, int out_size) {
    const float* x   = (const float*)d_in[0];
    const float* wq  = (const float*)d_in[1];
    const float* bq  = (const float*)d_in[2];
    const float* wk  = (const float*)d_in[3];
    const float* bk  = (const float*)d_in[4];
    const float* wv  = (const float*)d_in[5];
    const float* bv  = (const float*)d_in[6];
    const float* wo  = (const float*)d_in[7];
    const float* bo  = (const float*)d_in[8];
    const float* w1  = (const float*)d_in[9];
    const float* b1  = (const float*)d_in[10];
    const float* w2  = (const float*)d_in[11];
    const float* b2  = (const float*)d_in[12];
    const float* g1  = (const float*)d_in[13];
    const float* be1 = (const float*)d_in[14];
    const float* g2  = (const float*)d_in[15];
    const float* be2 = (const float*)d_in[16];

    __half *WqkvT, *WoT, *W1T, *W2T, *xh, *QKVh, *Oh, *Hhh, *FFh;
    float *Bqkv, *T, *Hh;
    cudaGetSymbolAddress((void**)&WqkvT, g_WqkvT);
    cudaGetSymbolAddress((void**)&Bqkv,  g_Bqkv);
    cudaGetSymbolAddress((void**)&WoT,   g_WoT);
    cudaGetSymbolAddress((void**)&W1T,   g_W1T);
    cudaGetSymbolAddress((void**)&W2T,   g_W2T);
    cudaGetSymbolAddress((void**)&xh,    g_xh);
    cudaGetSymbolAddress((void**)&QKVh,  g_QKVh);
    cudaGetSymbolAddress((void**)&Oh,    g_Oh);
    cudaGetSymbolAddress((void**)&T,     g_T);
    cudaGetSymbolAddress((void**)&Hh,    g_Hh);
    cudaGetSymbolAddress((void**)&Hhh,   g_Hhh);
    cudaGetSymbolAddress((void**)&FFh,   g_FFh);

    cudaFuncSetAttribute(hgemm<EPI_BIASH>, cudaFuncAttributeMaxDynamicSharedMemorySize, GEMM_SMEM);
    cudaFuncSetAttribute(hgemm<EPI_GELUH>, cudaFuncAttributeMaxDynamicSharedMemorySize, GEMM_SMEM);
    cudaFuncSetAttribute(hgemm<EPI_RES>,   cudaFuncAttributeMaxDynamicSharedMemorySize, GEMM_SMEM);
    cudaFuncSetAttribute(fattn, cudaFuncAttributeMaxDynamicSharedMemorySize, FA_SMEM);

    // 0) unified prologue: weight repacks + x -> fp16 in ONE launch
    prep<<<PB_TOTAL, 256>>>(x, wq, wk, wv, bq, bk, bv, wo, w1, w2);

    // 1) QKV projection -> fp16
    hgemm<EPI_BIASH><<<dim3(3 * Dn / 128, Mn / 128), 128, GEMM_SMEM>>>(
        xh, WqkvT, Bqkv, nullptr, nullptr, QKVh, Mn, 3 * Dn, Dn);
    // 2) tensor-core causal flash attention -> Oh (fp16)
    fattn<<<dim3(Sn / 128, 64), 256, FA_SMEM>>>(QKVh, Oh);
    // 3) O projection + residual x
    hgemm<EPI_RES><<<dim3(Dn / 128, Mn / 128), 128, GEMM_SMEM>>>(
        Oh, WoT, bo, x, T, nullptr, Mn, Dn, Dn);
    // 4) LayerNorm 1 (fp32 + fp16 twin)
    ln_kernel<<<Mn, 256>>>(T, g1, be1, Hh, Hhh);
    // 5) FFN up + exact GELU -> fp16
    hgemm<EPI_GELUH><<<dim3(FFn / 128, Mn / 128), 128, GEMM_SMEM>>>(
        Hhh, W1T, b1, nullptr, nullptr, FFh, Mn, FFn, Dn);
    // 6) FFN down + residual Hh
    hgemm<EPI_RES><<<dim3(Dn / 128, Mn / 128), 128, GEMM_SMEM>>>(
        FFh, W2T, b2, Hh, T, nullptr, Mn, Dn, FFn);
    // 7) LayerNorm 2 -> output
    ln_kernel<<<Mn, 256>>>(T, g2, be2, (float*)d_out, nullptr);
}